// round 14
// baseline (speedup 1.0000x reference)
#include <cuda_runtime.h>
#include <cuda_bf16.h>
#include <cuda_fp16.h>
#include <math_constants.h>

#define C_DIM 1024
#define C3    3072
#define NH    16
#define HD    64
#define B_SZ  2
#define T_SZ  2048
#define M_ROWS (B_SZ*T_SZ)

#define ATT_SCALE 0.5f
#define LOG2E 1.4426950408889634f
#define QSC (ATT_SCALE * LOG2E)

typedef unsigned long long u64;
typedef unsigned int u32;

// ---------------- scratch (no device allocation allowed) -------------------
__device__ __half g_q16[(size_t)M_ROWS * C_DIM];    // Q fp16, pre-scaled by QSC
__device__ __half g_k16[(size_t)M_ROWS * C_DIM];    // K single fp16
__device__ __half g_v16[(size_t)M_ROWS * C_DIM];    // V single fp16
__device__ __half g_xh16[(size_t)M_ROWS * C_DIM];   // x fp16 hi
__device__ __half g_xl16[(size_t)M_ROWS * C_DIM];   // x fp16 lo
__device__ __half g_o16[(size_t)M_ROWS * C_DIM];    // attn out single fp16
__device__ __half g_wq16[(size_t)C3 * C_DIM];       // Wqkv^T single fp16 [N][K]
__device__ __half g_wp16[(size_t)C_DIM * C_DIM];    // Wproj^T single fp16

// ---------------- helpers ----------------------------------------------------
__device__ __forceinline__ u32 smem_u32(const void* p) {
    u32 a; asm("{ .reg .u64 t; cvta.to.shared.u64 t, %1; cvt.u32.u64 %0, t; }"
               : "=r"(a) : "l"(p));
    return a;
}
__device__ __forceinline__ void ldsm_x4(u32& r0, u32& r1, u32& r2, u32& r3, u32 a) {
    asm volatile("ldmatrix.sync.aligned.m8n8.x4.shared.b16 {%0,%1,%2,%3}, [%4];"
                 : "=r"(r0), "=r"(r1), "=r"(r2), "=r"(r3) : "r"(a));
}
__device__ __forceinline__ void ldsm_x4t(u32& r0, u32& r1, u32& r2, u32& r3, u32 a) {
    asm volatile("ldmatrix.sync.aligned.m8n8.x4.trans.shared.b16 {%0,%1,%2,%3}, [%4];"
                 : "=r"(r0), "=r"(r1), "=r"(r2), "=r"(r3) : "r"(a));
}
__device__ __forceinline__ void mma16816h(float* c, const u32* a, const u32* b) {
    asm volatile(
        "mma.sync.aligned.m16n8k16.row.col.f32.f16.f16.f32 "
        "{%0,%1,%2,%3},{%4,%5,%6,%7},{%8,%9},{%0,%1,%2,%3};"
        : "+f"(c[0]), "+f"(c[1]), "+f"(c[2]), "+f"(c[3])
        : "r"(a[0]), "r"(a[1]), "r"(a[2]), "r"(a[3]), "r"(b[0]), "r"(b[1]));
}
__device__ __forceinline__ float fast_exp2(float x) {
    float r; asm("ex2.approx.ftz.f32 %0, %1;" : "=f"(r) : "f"(x)); return r;
}
__device__ __forceinline__ u32 cvt_f16x2(float lo, float hi) {
    u32 r; asm("cvt.rn.f16x2.f32 %0, %1, %2;" : "=r"(r) : "f"(hi), "f"(lo));
    return r;
}
__device__ __forceinline__ void split2h(float f0, float f1, u32& hi, u32& lo) {
    hi = cvt_f16x2(f0, f1);
    __half2 h2 = *reinterpret_cast<__half2*>(&hi);
    float2 hf = __half22float2(h2);
    lo = cvt_f16x2(f0 - hf.x, f1 - hf.y);
}
#define CP_ASYNC16(d, s) asm volatile("cp.async.cg.shared.global [%0], [%1], 16;" :: "r"(d), "l"(s))
#define CP_COMMIT()      asm volatile("cp.async.commit_group;" ::: "memory")
#define CP_WAIT1()       asm volatile("cp.async.wait_group 1;" ::: "memory")
#define CP_WAIT0()       asm volatile("cp.async.wait_group 0;" ::: "memory")

// ---------------- prep: fp32 -> fp16 hi/lo split -----------------------------
__global__ void split16_kernel(const float* __restrict__ in,
                               __half* __restrict__ hi,
                               __half* __restrict__ lo, int n4)
{
    int i = blockIdx.x * blockDim.x + threadIdx.x;
    if (i >= n4) return;
    float4 v = ((const float4*)in)[i];
    u32 h0, l0, h1, l1;
    split2h(v.x, v.y, h0, l0);
    split2h(v.z, v.w, h1, l1);
    ((uint2*)hi)[i] = make_uint2(h0, h1);
    ((uint2*)lo)[i] = make_uint2(l0, l1);
}

// ---------------- prep: W[K][N] -> W^T single fp16 [N][K] -------------------
__global__ void transpose_f16_kernel(const float* __restrict__ W,
                                     __half* __restrict__ W16, int K, int N)
{
    __shared__ float ts[32][33];
    int n0 = blockIdx.x * 32, k0 = blockIdx.y * 32;
    int tx = threadIdx.x, ty = threadIdx.y;  // 32 x 8
#pragma unroll
    for (int r = 0; r < 4; r++)
        ts[ty + 8 * r][tx] = W[(size_t)(k0 + ty + 8 * r) * N + n0 + tx];
    __syncthreads();
#pragma unroll
    for (int r = 0; r < 4; r++) {
        float v = ts[tx][ty + 8 * r];
        W16[(size_t)(n0 + ty + 8 * r) * K + k0 + tx] = __float2half_rn(v);
    }
}

// ---------------- fp16 GEMM: C = (A0 [+A1]) @ B16^T + bias ------------------
// NA = number of A passes (1 or 2), uniform for the whole launch.
// EPI 0: fp32 C out.
// EPI 1: fp16 out to q/k/v by global column part; Q part pre-scaled by QSC.
// n_off: global column offset of this launch (B16 and bias indexed globally).
#define RSTRIDE 80
#define ARR_B   (128 * RSTRIDE)

extern __shared__ char sm_raw[];

template<int NA, int EPI>
__global__ void __launch_bounds__(128) gemm_f16_kernel(
    const __half* __restrict__ A0, const __half* __restrict__ A1,
    const __half* __restrict__ B16,   // already offset to n_off
    const float* __restrict__ bias,   // full bias (global indexing)
    float* __restrict__ C,
    int M, int N, int K, int n_off,
    __half* oq16, __half* ok16, __half* ov16)
{
    const int STB = (NA + 1) * ARR_B;

    const int tid = threadIdx.x, lane = tid & 31, wid = tid >> 5;
    const int warp_m = wid & 1, warp_n = wid >> 1;
    const int m0 = blockIdx.y * 128, n0 = blockIdx.x * 128;

    const int grp = lane >> 3, lrow = lane & 7;
    const int a_row = (grp & 1) * 8 + lrow, a_kb = (grp >> 1) * 16;
    const int b_row = (grp >> 1) * 8 + lrow, b_kb = (grp & 1) * 16;

    float cf[4][8][4];
#pragma unroll
    for (int tm = 0; tm < 4; tm++)
#pragma unroll
        for (int tn = 0; tn < 8; tn++)
#pragma unroll
            for (int q = 0; q < 4; q++) cf[tm][tn][q] = 0.f;

#define G_LOAD(st, k0v)                                                         \
    do {                                                                        \
        char* _b = sm_raw + (st) * STB;                                         \
        _Pragma("unroll")                                                       \
        for (int j = 0; j < 4; j++) {                                           \
            int _i = tid + j * 128;                                             \
            int _r = _i >> 2, _c = _i & 3;                                      \
            u32 _d0 = smem_u32(_b + _r * RSTRIDE + _c * 16);                    \
            CP_ASYNC16(_d0, A0 + (size_t)(m0 + _r) * K + (k0v) + _c * 8);       \
            u32 _db = smem_u32(_b + NA * ARR_B + _r * RSTRIDE + _c * 16);       \
            CP_ASYNC16(_db, B16 + (size_t)(n0 + _r) * K + (k0v) + _c * 8);      \
            if (NA == 2) {                                                      \
                u32 _d1 = smem_u32(_b + ARR_B + _r * RSTRIDE + _c * 16);        \
                CP_ASYNC16(_d1, A1 + (size_t)(m0 + _r) * K + (k0v) + _c * 8);   \
            }                                                                   \
        }                                                                       \
    } while (0)

#define G_COMPUTE(st)                                                           \
    do {                                                                        \
        u32 _sb = smem_u32(sm_raw) + (st) * STB;                                \
        _Pragma("unroll")                                                       \
        for (int ks = 0; ks < 2; ks++) {                                        \
            u32 afr[NA][4][4], bfr[4][4];                                       \
            _Pragma("unroll")                                                   \
            for (int s = 0; s < NA; s++)                                        \
                _Pragma("unroll")                                               \
                for (int tm = 0; tm < 4; tm++)                                  \
                    ldsm_x4(afr[s][tm][0], afr[s][tm][1],                       \
                            afr[s][tm][2], afr[s][tm][3],                       \
                            _sb + s * ARR_B +                                   \
                            (warp_m * 64 + tm * 16 + a_row) * RSTRIDE +         \
                            ks * 32 + a_kb);                                    \
            _Pragma("unroll")                                                   \
            for (int t2 = 0; t2 < 4; t2++)                                      \
                ldsm_x4(bfr[t2][0], bfr[t2][1], bfr[t2][2], bfr[t2][3],         \
                        _sb + NA * ARR_B +                                      \
                        (warp_n * 64 + t2 * 16 + b_row) * RSTRIDE +             \
                        ks * 32 + b_kb);                                        \
            _Pragma("unroll")                                                   \
            for (int s = 0; s < NA; s++)                                        \
                _Pragma("unroll")                                               \
                for (int tm = 0; tm < 4; tm++)                                  \
                    _Pragma("unroll")                                           \
                    for (int tn = 0; tn < 8; tn++)                              \
                        mma16816h(cf[tm][tn], afr[s][tm],                       \
                                  &bfr[tn >> 1][(tn & 1) * 2]);                 \
        }                                                                       \
    } while (0)

    const int NIT = K / 32;
    G_LOAD(0, 0);
    CP_COMMIT();
    for (int it = 0; it < NIT; it++) {
        if (it + 1 < NIT) {
            G_LOAD((it + 1) & 1, (it + 1) * 32);
            CP_COMMIT();
            CP_WAIT1();
        } else {
            CP_WAIT0();
        }
        __syncthreads();
        G_COMPUTE(it & 1);
        __syncthreads();
    }

    const int mrow = lane >> 2, ncol = (lane & 3) * 2;
    if (EPI == 0) {
#pragma unroll
        for (int tm = 0; tm < 4; tm++)
#pragma unroll
            for (int tn = 0; tn < 8; tn++) {
                int r = m0 + warp_m * 64 + tm * 16 + mrow;
                int c = n0 + warp_n * 64 + tn * 8 + ncol;
                float2 bb = *(const float2*)&bias[c];
                *(float2*)&C[(size_t)r * N + c] =
                    make_float2(cf[tm][tn][0] + bb.x, cf[tm][tn][1] + bb.y);
                *(float2*)&C[(size_t)(r + 8) * N + c] =
                    make_float2(cf[tm][tn][2] + bb.x, cf[tm][tn][3] + bb.y);
            }
    } else {
#pragma unroll
        for (int tm = 0; tm < 4; tm++)
#pragma unroll
            for (int tn = 0; tn < 8; tn++) {
                int r = m0 + warp_m * 64 + tm * 16 + mrow;
                int gc = n_off + n0 + warp_n * 64 + tn * 8 + ncol;
                int part = gc >> 10;
                int lc = gc & 1023;
                __half* dst = part == 0 ? oq16 : (part == 1 ? ok16 : ov16);
                float sc = part == 0 ? QSC : 1.0f;
                float2 bb = *(const float2*)&bias[gc];
                u32 v0 = cvt_f16x2((cf[tm][tn][0] + bb.x) * sc,
                                   (cf[tm][tn][1] + bb.y) * sc);
                u32 v1 = cvt_f16x2((cf[tm][tn][2] + bb.x) * sc,
                                   (cf[tm][tn][3] + bb.y) * sc);
                *(u32*)(dst + (size_t)r * C_DIM + lc) = v0;
                *(u32*)(dst + (size_t)(r + 8) * C_DIM + lc) = v1;
            }
    }
#undef G_LOAD
#undef G_COMPUTE
}

// ---------------- tensor-core flash attention -------------------------------
// S = Qs @ K16^T (Q pre-scaled by QSC -> logits already in exp2 domain).
// PV = P16 @ V16 (single pass).
#define FA_RS   72
#define FA_ARR  (128 * FA_RS)
#define FA_ST0  FA_ARR
#define FA_STSZ (2 * FA_ARR)
#define FA_SMEM ((FA_ARR + 2 * FA_STSZ) * 2)   // 92160 B -> 2 CTAs/SM

__global__ void __launch_bounds__(256) flash_attn_mma(
    const __half* __restrict__ q16, const __half* __restrict__ k16,
    const __half* __restrict__ v16, __half* __restrict__ o16)
{
    __half* sm = (__half*)sm_raw;
    const int tid = threadIdx.x, lane = tid & 31, w = tid >> 5;
    const int qt = blockIdx.x;
    const int b = blockIdx.y >> 4, h = blockIdx.y & 15;
    const size_t rowbase = (size_t)b * T_SZ;
    const int colbase = h * HD;

    const __half* kvsrc[2] = {k16, v16};

#define FA_LOAD(st, kt)                                                         \
    do {                                                                        \
        _Pragma("unroll")                                                       \
        for (int a4 = 0; a4 < 2; a4++) {                                        \
            _Pragma("unroll")                                                   \
            for (int j = 0; j < 4; j++) {                                       \
                int idx = tid + j * 256;                                        \
                int r = idx >> 3, c8 = idx & 7;                                 \
                u32 d = smem_u32(sm + FA_ST0 + (st) * FA_STSZ + a4 * FA_ARR +   \
                                 r * FA_RS + c8 * 8);                           \
                CP_ASYNC16(d, kvsrc[a4] +                                       \
                           (rowbase + (kt) * 128 + r) * C_DIM + colbase + c8 * 8); \
            }                                                                   \
        }                                                                       \
    } while (0)

    FA_LOAD(0, 0);
    CP_COMMIT();

    // stage Q (pre-scaled fp16)
#pragma unroll
    for (int j = 0; j < 4; j++) {
        int idx = tid + j * 256;
        int r = idx >> 3, c8 = idx & 7;
        uint4 v = *(const uint4*)(q16 +
            (rowbase + qt * 128 + r) * C_DIM + colbase + c8 * 8);
        *(uint4*)(sm + r * FA_RS + c8 * 8) = v;
    }
    __syncthreads();

    u32 qf[4][4];
    {
        u32 qbase = smem_u32(sm);
        int arow = w * 16 + (lane & 15);
        int acol = (lane >> 4) * 8;
#pragma unroll
        for (int ks = 0; ks < 4; ks++) {
            u32 off = (arow * FA_RS + ks * 16 + acol) * 2;
            ldsm_x4(qf[ks][0], qf[ks][1], qf[ks][2], qf[ks][3], qbase + off);
        }
    }

    float sf[16][4];
    float of[8][4];
#pragma unroll
    for (int j = 0; j < 8; j++)
#pragma unroll
        for (int q = 0; q < 4; q++) of[j][q] = 0.f;
    float m0 = -CUDART_INF_F, m1 = -CUDART_INF_F, l0 = 0.f, l1 = 0.f;

    const u32 sbase = smem_u32(sm);
    const int krow = (lane & 7) + ((lane >> 4) << 3);
    const int kch  = (lane >> 3) & 1;
    const int vrow = (lane & 7) + (((lane >> 3) & 1) << 3);
    const int vch  = lane >> 4;

    for (int kt = 0; kt < T_SZ / 128; kt++) {
        if (kt + 1 < T_SZ / 128) { FA_LOAD((kt + 1) & 1, kt + 1); CP_COMMIT(); CP_WAIT1(); }
        else CP_WAIT0();
        __syncthreads();
        u32 stb = sbase + (FA_ST0 + (kt & 1) * FA_STSZ) * 2;

        // ---- S = Qs K^T (single fp16 pass, exp2-domain logits) ----
#pragma unroll
        for (int j = 0; j < 16; j++) {
            sf[j][0] = 0.f; sf[j][1] = 0.f; sf[j][2] = 0.f; sf[j][3] = 0.f;
        }
#pragma unroll
        for (int jp = 0; jp < 4; jp++) {
            u32 bh[2][4][4];
#pragma unroll
            for (int j2 = 0; j2 < 2; j2++)
#pragma unroll
                for (int ks = 0; ks < 4; ks++) {
                    u32 off = (((jp * 2 + j2) * 16 + krow) * FA_RS +
                               ks * 16 + kch * 8) * 2;
                    ldsm_x4(bh[j2][ks][0], bh[j2][ks][1], bh[j2][ks][2], bh[j2][ks][3],
                            stb + off);
                }
            float* s0 = sf[4 * jp];     float* s1 = sf[4 * jp + 1];
            float* s2 = sf[4 * jp + 2]; float* s3 = sf[4 * jp + 3];
#pragma unroll
            for (int ks = 0; ks < 4; ks++) {
                mma16816h(s0, qf[ks], &bh[0][ks][0]);
                mma16816h(s1, qf[ks], &bh[0][ks][2]);
                mma16816h(s2, qf[ks], &bh[1][ks][0]);
                mma16816h(s3, qf[ks], &bh[1][ks][2]);
            }
        }

        // ---- online softmax (no scale multiply; logits already exp2-domain) ----
        float mt0 = -CUDART_INF_F, mt1 = -CUDART_INF_F;
#pragma unroll
        for (int j = 0; j < 16; j++) {
            mt0 = fmaxf(mt0, fmaxf(sf[j][0], sf[j][1]));
            mt1 = fmaxf(mt1, fmaxf(sf[j][2], sf[j][3]));
        }
        mt0 = fmaxf(mt0, __shfl_xor_sync(0xffffffffu, mt0, 1));
        mt0 = fmaxf(mt0, __shfl_xor_sync(0xffffffffu, mt0, 2));
        mt1 = fmaxf(mt1, __shfl_xor_sync(0xffffffffu, mt1, 1));
        mt1 = fmaxf(mt1, __shfl_xor_sync(0xffffffffu, mt1, 2));
        float mn0 = fmaxf(m0, mt0), mn1 = fmaxf(m1, mt1);
        float f0 = fast_exp2(m0 - mn0), f1 = fast_exp2(m1 - mn1);
        m0 = mn0; m1 = mn1;
        float rs0 = 0.f, rs1 = 0.f;
#pragma unroll
        for (int j = 0; j < 16; j++) {
            sf[j][0] = fast_exp2(sf[j][0] - mn0);
            sf[j][1] = fast_exp2(sf[j][1] - mn0);
            sf[j][2] = fast_exp2(sf[j][2] - mn1);
            sf[j][3] = fast_exp2(sf[j][3] - mn1);
            rs0 += sf[j][0] + sf[j][1];
            rs1 += sf[j][2] + sf[j][3];
        }
        rs0 += __shfl_xor_sync(0xffffffffu, rs0, 1);
        rs0 += __shfl_xor_sync(0xffffffffu, rs0, 2);
        rs1 += __shfl_xor_sync(0xffffffffu, rs1, 1);
        rs1 += __shfl_xor_sync(0xffffffffu, rs1, 2);
        l0 = l0 * f0 + rs0;
        l1 = l1 * f1 + rs1;
#pragma unroll
        for (int j = 0; j < 8; j++) {
            of[j][0] *= f0; of[j][1] *= f0; of[j][2] *= f1; of[j][3] *= f1;
        }

        // ---- O += P V (single fp16 pass) ----
#pragma unroll
        for (int kp = 0; kp < 8; kp++) {
            u32 ah[4];
            ah[0] = cvt_f16x2(sf[2 * kp][0],     sf[2 * kp][1]);
            ah[1] = cvt_f16x2(sf[2 * kp][2],     sf[2 * kp][3]);
            ah[2] = cvt_f16x2(sf[2 * kp + 1][0], sf[2 * kp + 1][1]);
            ah[3] = cvt_f16x2(sf[2 * kp + 1][2], sf[2 * kp + 1][3]);
            u32 bv[4][4];
#pragma unroll
            for (int dt = 0; dt < 4; dt++) {
                u32 off = ((kp * 16 + vrow) * FA_RS + dt * 16 + vch * 8) * 2;
                ldsm_x4t(bv[dt][0], bv[dt][1], bv[dt][2], bv[dt][3],
                         stb + FA_ARR * 2 + off);
            }
#pragma unroll
            for (int dt = 0; dt < 4; dt++) {
                mma16816h(of[2 * dt],     ah, &bv[dt][0]);
                mma16816h(of[2 * dt + 1], ah, &bv[dt][2]);
            }
        }
        __syncthreads();
    }

    // ---- epilogue: normalize, store single fp16 ----
    float inv0 = 1.f / l0, inv1 = 1.f / l1;
    const int g = lane >> 2, t2 = (lane & 3) * 2;
    size_t r0 = rowbase + qt * 128 + w * 16 + g;
#pragma unroll
    for (int j = 0; j < 8; j++) {
        int c = colbase + j * 8 + t2;
        u32 v0 = cvt_f16x2(of[j][0] * inv0, of[j][1] * inv0);
        u32 v1 = cvt_f16x2(of[j][2] * inv1, of[j][3] * inv1);
        *(u32*)(o16 + r0 * C_DIM + c) = v0;
        *(u32*)(o16 + (r0 + 8) * C_DIM + c) = v1;
    }
#undef FA_LOAD
}

// ---------------------------------------------------------------------------
extern "C" void kernel_launch(void* const* d_in, const int* in_sizes, int n_in,
                              void* d_out, int out_size)
{
    const float* x     = (const float*)d_in[0];
    const float* Wqkv  = (const float*)d_in[1];
    const float* bqkv  = (const float*)d_in[2];
    const float* Wproj = (const float*)d_in[3];
    const float* bproj = (const float*)d_in[4];
    float* out = (float*)d_out;

    __half *q16, *k16, *v16, *xh16, *xl16, *o16, *wq16, *wp16;
    cudaGetSymbolAddress((void**)&q16, g_q16);
    cudaGetSymbolAddress((void**)&k16, g_k16);   cudaGetSymbolAddress((void**)&v16, g_v16);
    cudaGetSymbolAddress((void**)&xh16, g_xh16); cudaGetSymbolAddress((void**)&xl16, g_xl16);
    cudaGetSymbolAddress((void**)&o16, g_o16);
    cudaGetSymbolAddress((void**)&wq16, g_wq16); cudaGetSymbolAddress((void**)&wp16, g_wp16);

    const int SM_2P = 2 * 3 * ARR_B;   // NA=2: A0,A1,B x2 stages = 61440 B
    const int SM_1P = 2 * 2 * ARR_B;   // NA=1: A0,B  x2 stages = 40960 B
    cudaFuncSetAttribute(gemm_f16_kernel<2, 1>,
                         cudaFuncAttributeMaxDynamicSharedMemorySize, SM_2P);
    cudaFuncSetAttribute(gemm_f16_kernel<1, 1>,
                         cudaFuncAttributeMaxDynamicSharedMemorySize, SM_1P);
    cudaFuncSetAttribute(gemm_f16_kernel<1, 0>,
                         cudaFuncAttributeMaxDynamicSharedMemorySize, SM_1P);
    cudaFuncSetAttribute(flash_attn_mma,
                         cudaFuncAttributeMaxDynamicSharedMemorySize, FA_SMEM);

    // prep: x -> fp16 hi/lo; weights -> transposed single fp16
    split16_kernel<<<(M_ROWS * C_DIM / 4 + 255) / 256, 256>>>(
        x, xh16, xl16, M_ROWS * C_DIM / 4);
    transpose_f16_kernel<<<dim3(C3 / 32, C_DIM / 32), dim3(32, 8)>>>(
        Wqkv, wq16, C_DIM, C3);
    transpose_f16_kernel<<<dim3(C_DIM / 32, C_DIM / 32), dim3(32, 8)>>>(
        Wproj, wp16, C_DIM, C_DIM);

    // 1a) Q projection (x 2-pass), output pre-scaled by QSC
    gemm_f16_kernel<2, 1><<<dim3(C_DIM / 128, M_ROWS / 128), 128, SM_2P>>>(
        xh16, xl16, wq16, bqkv, nullptr, M_ROWS, C_DIM, C_DIM, 0,
        q16, k16, v16);

    // 1b) K,V projection (x single-pass)
    gemm_f16_kernel<1, 1><<<dim3(2 * C_DIM / 128, M_ROWS / 128), 128, SM_1P>>>(
        xh16, nullptr, wq16 + (size_t)C_DIM * C_DIM, bqkv, nullptr,
        M_ROWS, 2 * C_DIM, C_DIM, C_DIM,
        q16, k16, v16);

    // 2) attention -> single fp16
    flash_attn_mma<<<dim3(T_SZ / 128, B_SZ * NH), 256, FA_SMEM>>>(
        q16, k16, v16, o16);

    // 3) out = attn @ Wproj + bproj (fp16 single-pass)
    gemm_f16_kernel<1, 0><<<dim3(C_DIM / 128, M_ROWS / 128), 128, SM_1P>>>(
        o16, nullptr, wp16, bproj, out, M_ROWS, C_DIM, C_DIM, 0,
        nullptr, nullptr, nullptr);
}

// round 15
// speedup vs baseline: 1.0094x; 1.0094x over previous
#include <cuda_runtime.h>
#include <cuda_bf16.h>
#include <cuda_fp16.h>
#include <math_constants.h>

#define C_DIM 1024
#define C3    3072
#define NH    16
#define HD    64
#define B_SZ  2
#define T_SZ  2048
#define M_ROWS (B_SZ*T_SZ)

#define ATT_SCALE 0.5f
#define LOG2E 1.4426950408889634f
#define QSC (ATT_SCALE * LOG2E)

typedef unsigned long long u64;
typedef unsigned int u32;

// ---------------- scratch (no device allocation allowed) -------------------
__device__ __half g_q16[(size_t)M_ROWS * C_DIM];    // Q fp16, pre-scaled by QSC
__device__ __half g_k16[(size_t)M_ROWS * C_DIM];    // K single fp16
__device__ __half g_v16[(size_t)M_ROWS * C_DIM];    // V single fp16
__device__ __half g_xh16[(size_t)M_ROWS * C_DIM];   // x fp16 hi
__device__ __half g_xl16[(size_t)M_ROWS * C_DIM];   // x fp16 lo
__device__ __half g_o16[(size_t)M_ROWS * C_DIM];    // attn out single fp16
__device__ __half g_wq16[(size_t)C3 * C_DIM];       // Wqkv^T single fp16 [N][K]
__device__ __half g_wp16[(size_t)C_DIM * C_DIM];    // Wproj^T single fp16

// ---------------- helpers ----------------------------------------------------
__device__ __forceinline__ u32 smem_u32(const void* p) {
    u32 a; asm("{ .reg .u64 t; cvta.to.shared.u64 t, %1; cvt.u32.u64 %0, t; }"
               : "=r"(a) : "l"(p));
    return a;
}
__device__ __forceinline__ void ldsm_x4(u32& r0, u32& r1, u32& r2, u32& r3, u32 a) {
    asm volatile("ldmatrix.sync.aligned.m8n8.x4.shared.b16 {%0,%1,%2,%3}, [%4];"
                 : "=r"(r0), "=r"(r1), "=r"(r2), "=r"(r3) : "r"(a));
}
__device__ __forceinline__ void ldsm_x4t(u32& r0, u32& r1, u32& r2, u32& r3, u32 a) {
    asm volatile("ldmatrix.sync.aligned.m8n8.x4.trans.shared.b16 {%0,%1,%2,%3}, [%4];"
                 : "=r"(r0), "=r"(r1), "=r"(r2), "=r"(r3) : "r"(a));
}
__device__ __forceinline__ void mma16816h(float* c, const u32* a, const u32* b) {
    asm volatile(
        "mma.sync.aligned.m16n8k16.row.col.f32.f16.f16.f32 "
        "{%0,%1,%2,%3},{%4,%5,%6,%7},{%8,%9},{%0,%1,%2,%3};"
        : "+f"(c[0]), "+f"(c[1]), "+f"(c[2]), "+f"(c[3])
        : "r"(a[0]), "r"(a[1]), "r"(a[2]), "r"(a[3]), "r"(b[0]), "r"(b[1]));
}
__device__ __forceinline__ float fast_exp2(float x) {
    float r; asm("ex2.approx.ftz.f32 %0, %1;" : "=f"(r) : "f"(x)); return r;
}
__device__ __forceinline__ u32 cvt_f16x2(float lo, float hi) {
    u32 r; asm("cvt.rn.f16x2.f32 %0, %1, %2;" : "=r"(r) : "f"(hi), "f"(lo));
    return r;
}
__device__ __forceinline__ void split2h(float f0, float f1, u32& hi, u32& lo) {
    hi = cvt_f16x2(f0, f1);
    __half2 h2 = *reinterpret_cast<__half2*>(&hi);
    float2 hf = __half22float2(h2);
    lo = cvt_f16x2(f0 - hf.x, f1 - hf.y);
}
#define CP_ASYNC16(d, s) asm volatile("cp.async.cg.shared.global [%0], [%1], 16;" :: "r"(d), "l"(s))
#define CP_COMMIT()      asm volatile("cp.async.commit_group;" ::: "memory")
#define CP_WAIT1()       asm volatile("cp.async.wait_group 1;" ::: "memory")
#define CP_WAIT0()       asm volatile("cp.async.wait_group 0;" ::: "memory")

// ---------------- prep: fp32 -> fp16 hi/lo split -----------------------------
__global__ void split16_kernel(const float* __restrict__ in,
                               __half* __restrict__ hi,
                               __half* __restrict__ lo, int n4)
{
    int i = blockIdx.x * blockDim.x + threadIdx.x;
    if (i >= n4) return;
    float4 v = ((const float4*)in)[i];
    u32 h0, l0, h1, l1;
    split2h(v.x, v.y, h0, l0);
    split2h(v.z, v.w, h1, l1);
    ((uint2*)hi)[i] = make_uint2(h0, h1);
    ((uint2*)lo)[i] = make_uint2(l0, l1);
}

// ---------------- prep: W[K][N] -> W^T single fp16 [N][K] -------------------
__global__ void transpose_f16_kernel(const float* __restrict__ W,
                                     __half* __restrict__ W16, int K, int N)
{
    __shared__ float ts[32][33];
    int n0 = blockIdx.x * 32, k0 = blockIdx.y * 32;
    int tx = threadIdx.x, ty = threadIdx.y;  // 32 x 8
#pragma unroll
    for (int r = 0; r < 4; r++)
        ts[ty + 8 * r][tx] = W[(size_t)(k0 + ty + 8 * r) * N + n0 + tx];
    __syncthreads();
#pragma unroll
    for (int r = 0; r < 4; r++) {
        float v = ts[tx][ty + 8 * r];
        W16[(size_t)(n0 + ty + 8 * r) * K + k0 + tx] = __float2half_rn(v);
    }
}

// ---------------- fp16 GEMM: C = (A0 [+A1]) @ B16^T + bias ------------------
// NA=2 + REMAP=1 (QKV): block column remapped so each scheduled trio has one
// heavy (2-pass Q) block; A1 pass applied only for Q columns (n0 < C_DIM).
// EPI 0: fp32 C out.  EPI 1: q/k/v fp16 out by column part; Q pre-scaled QSC.
#define RSTRIDE 80
#define ARR_B   (128 * RSTRIDE)

extern __shared__ char sm_raw[];

template<int NA, int EPI, int REMAP>
__global__ void __launch_bounds__(128) gemm_f16_kernel(
    const __half* __restrict__ A0, const __half* __restrict__ A1,
    const __half* __restrict__ B16,
    const float* __restrict__ bias, float* __restrict__ C,
    int M, int N, int K,
    __half* oq16, __half* ok16, __half* ov16)
{
    const int STB = (NA + 1) * ARR_B;

    const int tid = threadIdx.x, lane = tid & 31, wid = tid >> 5;
    const int warp_m = wid & 1, warp_n = wid >> 1;
    const int m0 = blockIdx.y * 128;
    // Interleave heavy/light blocks: nb = (bx%3)*8 + bx/3  (Q blocks = nb 0..7)
    const int bx = blockIdx.x;
    const int nb = REMAP ? ((bx % 3) * 8 + bx / 3) : bx;
    const int n0 = nb * 128;

    // 2nd A pass only for Q columns; uniform per block.
    const bool useA1 = (NA == 2) && (n0 < C_DIM);

    const int grp = lane >> 3, lrow = lane & 7;
    const int a_row = (grp & 1) * 8 + lrow, a_kb = (grp >> 1) * 16;
    const int b_row = (grp >> 1) * 8 + lrow, b_kb = (grp & 1) * 16;

    float cf[4][8][4];
#pragma unroll
    for (int tm = 0; tm < 4; tm++)
#pragma unroll
        for (int tn = 0; tn < 8; tn++)
#pragma unroll
            for (int q = 0; q < 4; q++) cf[tm][tn][q] = 0.f;

#define G_LOAD(st, k0v)                                                         \
    do {                                                                        \
        char* _b = sm_raw + (st) * STB;                                         \
        _Pragma("unroll")                                                       \
        for (int j = 0; j < 4; j++) {                                           \
            int _i = tid + j * 128;                                             \
            int _r = _i >> 2, _c = _i & 3;                                      \
            u32 _d0 = smem_u32(_b + _r * RSTRIDE + _c * 16);                    \
            CP_ASYNC16(_d0, A0 + (size_t)(m0 + _r) * K + (k0v) + _c * 8);       \
            u32 _db = smem_u32(_b + NA * ARR_B + _r * RSTRIDE + _c * 16);       \
            CP_ASYNC16(_db, B16 + (size_t)(n0 + _r) * K + (k0v) + _c * 8);      \
            if (useA1) {                                                        \
                u32 _d1 = smem_u32(_b + ARR_B + _r * RSTRIDE + _c * 16);        \
                CP_ASYNC16(_d1, A1 + (size_t)(m0 + _r) * K + (k0v) + _c * 8);   \
            }                                                                   \
        }                                                                       \
    } while (0)

#define G_COMPUTE(st)                                                           \
    do {                                                                        \
        u32 _sb = smem_u32(sm_raw) + (st) * STB;                                \
        _Pragma("unroll")                                                       \
        for (int ks = 0; ks < 2; ks++) {                                        \
            u32 afr0[4][4], bfr[4][4];                                          \
            _Pragma("unroll")                                                   \
            for (int tm = 0; tm < 4; tm++)                                      \
                ldsm_x4(afr0[tm][0], afr0[tm][1], afr0[tm][2], afr0[tm][3],     \
                        _sb + (warp_m * 64 + tm * 16 + a_row) * RSTRIDE +       \
                        ks * 32 + a_kb);                                        \
            _Pragma("unroll")                                                   \
            for (int t2 = 0; t2 < 4; t2++)                                      \
                ldsm_x4(bfr[t2][0], bfr[t2][1], bfr[t2][2], bfr[t2][3],         \
                        _sb + NA * ARR_B +                                      \
                        (warp_n * 64 + t2 * 16 + b_row) * RSTRIDE +             \
                        ks * 32 + b_kb);                                        \
            _Pragma("unroll")                                                   \
            for (int tm = 0; tm < 4; tm++)                                      \
                _Pragma("unroll")                                               \
                for (int tn = 0; tn < 8; tn++)                                  \
                    mma16816h(cf[tm][tn], afr0[tm],                             \
                              &bfr[tn >> 1][(tn & 1) * 2]);                     \
            if (useA1) {                                                        \
                u32 afr1[4][4];                                                 \
                _Pragma("unroll")                                               \
                for (int tm = 0; tm < 4; tm++)                                  \
                    ldsm_x4(afr1[tm][0], afr1[tm][1], afr1[tm][2], afr1[tm][3], \
                            _sb + ARR_B +                                       \
                            (warp_m * 64 + tm * 16 + a_row) * RSTRIDE +         \
                            ks * 32 + a_kb);                                    \
                _Pragma("unroll")                                               \
                for (int tm = 0; tm < 4; tm++)                                  \
                    _Pragma("unroll")                                           \
                    for (int tn = 0; tn < 8; tn++)                              \
                        mma16816h(cf[tm][tn], afr1[tm],                         \
                                  &bfr[tn >> 1][(tn & 1) * 2]);                 \
            }                                                                   \
        }                                                                       \
    } while (0)

    const int NIT = K / 32;
    G_LOAD(0, 0);
    CP_COMMIT();
    for (int it = 0; it < NIT; it++) {
        if (it + 1 < NIT) {
            G_LOAD((it + 1) & 1, (it + 1) * 32);
            CP_COMMIT();
            CP_WAIT1();
        } else {
            CP_WAIT0();
        }
        __syncthreads();
        G_COMPUTE(it & 1);
        __syncthreads();
    }

    const int mrow = lane >> 2, ncol = (lane & 3) * 2;
    if (EPI == 0) {
#pragma unroll
        for (int tm = 0; tm < 4; tm++)
#pragma unroll
            for (int tn = 0; tn < 8; tn++) {
                int r = m0 + warp_m * 64 + tm * 16 + mrow;
                int c = n0 + warp_n * 64 + tn * 8 + ncol;
                float2 bb = *(const float2*)&bias[c];
                *(float2*)&C[(size_t)r * N + c] =
                    make_float2(cf[tm][tn][0] + bb.x, cf[tm][tn][1] + bb.y);
                *(float2*)&C[(size_t)(r + 8) * N + c] =
                    make_float2(cf[tm][tn][2] + bb.x, cf[tm][tn][3] + bb.y);
            }
    } else {
        int part = n0 >> 10;
        __half* dst = part == 0 ? oq16 : (part == 1 ? ok16 : ov16);
        float sc = part == 0 ? QSC : 1.0f;
#pragma unroll
        for (int tm = 0; tm < 4; tm++)
#pragma unroll
            for (int tn = 0; tn < 8; tn++) {
                int r = m0 + warp_m * 64 + tm * 16 + mrow;
                int c = n0 + warp_n * 64 + tn * 8 + ncol;
                int lc = c & 1023;
                float2 bb = *(const float2*)&bias[c];
                u32 v0 = cvt_f16x2((cf[tm][tn][0] + bb.x) * sc,
                                   (cf[tm][tn][1] + bb.y) * sc);
                u32 v1 = cvt_f16x2((cf[tm][tn][2] + bb.x) * sc,
                                   (cf[tm][tn][3] + bb.y) * sc);
                *(u32*)(dst + (size_t)r * C_DIM + lc) = v0;
                *(u32*)(dst + (size_t)(r + 8) * C_DIM + lc) = v1;
            }
    }
#undef G_LOAD
#undef G_COMPUTE
}

// ---------------- tensor-core flash attention -------------------------------
// S = Qs @ K16^T (Q pre-scaled -> logits already exp2-domain). PV = P16 @ V16.
#define FA_RS   72
#define FA_ARR  (128 * FA_RS)
#define FA_ST0  FA_ARR
#define FA_STSZ (2 * FA_ARR)
#define FA_SMEM ((FA_ARR + 2 * FA_STSZ) * 2)   // 92160 B -> 2 CTAs/SM

__global__ void __launch_bounds__(256) flash_attn_mma(
    const __half* __restrict__ q16, const __half* __restrict__ k16,
    const __half* __restrict__ v16, __half* __restrict__ o16)
{
    __half* sm = (__half*)sm_raw;
    const int tid = threadIdx.x, lane = tid & 31, w = tid >> 5;
    const int qt = blockIdx.x;
    const int b = blockIdx.y >> 4, h = blockIdx.y & 15;
    const size_t rowbase = (size_t)b * T_SZ;
    const int colbase = h * HD;

    const __half* kvsrc[2] = {k16, v16};

#define FA_LOAD(st, kt)                                                         \
    do {                                                                        \
        _Pragma("unroll")                                                       \
        for (int a4 = 0; a4 < 2; a4++) {                                        \
            _Pragma("unroll")                                                   \
            for (int j = 0; j < 4; j++) {                                       \
                int idx = tid + j * 256;                                        \
                int r = idx >> 3, c8 = idx & 7;                                 \
                u32 d = smem_u32(sm + FA_ST0 + (st) * FA_STSZ + a4 * FA_ARR +   \
                                 r * FA_RS + c8 * 8);                           \
                CP_ASYNC16(d, kvsrc[a4] +                                       \
                           (rowbase + (kt) * 128 + r) * C_DIM + colbase + c8 * 8); \
            }                                                                   \
        }                                                                       \
    } while (0)

    FA_LOAD(0, 0);
    CP_COMMIT();

    // stage Q (pre-scaled fp16)
#pragma unroll
    for (int j = 0; j < 4; j++) {
        int idx = tid + j * 256;
        int r = idx >> 3, c8 = idx & 7;
        uint4 v = *(const uint4*)(q16 +
            (rowbase + qt * 128 + r) * C_DIM + colbase + c8 * 8);
        *(uint4*)(sm + r * FA_RS + c8 * 8) = v;
    }
    __syncthreads();

    u32 qf[4][4];
    {
        u32 qbase = smem_u32(sm);
        int arow = w * 16 + (lane & 15);
        int acol = (lane >> 4) * 8;
#pragma unroll
        for (int ks = 0; ks < 4; ks++) {
            u32 off = (arow * FA_RS + ks * 16 + acol) * 2;
            ldsm_x4(qf[ks][0], qf[ks][1], qf[ks][2], qf[ks][3], qbase + off);
        }
    }

    float sf[16][4];
    float of[8][4];
#pragma unroll
    for (int j = 0; j < 8; j++)
#pragma unroll
        for (int q = 0; q < 4; q++) of[j][q] = 0.f;
    float m0 = -CUDART_INF_F, m1 = -CUDART_INF_F, l0 = 0.f, l1 = 0.f;

    const u32 sbase = smem_u32(sm);
    const int krow = (lane & 7) + ((lane >> 4) << 3);
    const int kch  = (lane >> 3) & 1;
    const int vrow = (lane & 7) + (((lane >> 3) & 1) << 3);
    const int vch  = lane >> 4;

    for (int kt = 0; kt < T_SZ / 128; kt++) {
        if (kt + 1 < T_SZ / 128) { FA_LOAD((kt + 1) & 1, kt + 1); CP_COMMIT(); CP_WAIT1(); }
        else CP_WAIT0();
        __syncthreads();
        u32 stb = sbase + (FA_ST0 + (kt & 1) * FA_STSZ) * 2;

        // ---- S = Qs K^T (single fp16 pass, exp2-domain logits) ----
#pragma unroll
        for (int j = 0; j < 16; j++) {
            sf[j][0] = 0.f; sf[j][1] = 0.f; sf[j][2] = 0.f; sf[j][3] = 0.f;
        }
#pragma unroll
        for (int jp = 0; jp < 4; jp++) {
            u32 bh[2][4][4];
#pragma unroll
            for (int j2 = 0; j2 < 2; j2++)
#pragma unroll
                for (int ks = 0; ks < 4; ks++) {
                    u32 off = (((jp * 2 + j2) * 16 + krow) * FA_RS +
                               ks * 16 + kch * 8) * 2;
                    ldsm_x4(bh[j2][ks][0], bh[j2][ks][1], bh[j2][ks][2], bh[j2][ks][3],
                            stb + off);
                }
            float* s0 = sf[4 * jp];     float* s1 = sf[4 * jp + 1];
            float* s2 = sf[4 * jp + 2]; float* s3 = sf[4 * jp + 3];
#pragma unroll
            for (int ks = 0; ks < 4; ks++) {
                mma16816h(s0, qf[ks], &bh[0][ks][0]);
                mma16816h(s1, qf[ks], &bh[0][ks][2]);
                mma16816h(s2, qf[ks], &bh[1][ks][0]);
                mma16816h(s3, qf[ks], &bh[1][ks][2]);
            }
        }

        // ---- online softmax ----
        float mt0 = -CUDART_INF_F, mt1 = -CUDART_INF_F;
#pragma unroll
        for (int j = 0; j < 16; j++) {
            mt0 = fmaxf(mt0, fmaxf(sf[j][0], sf[j][1]));
            mt1 = fmaxf(mt1, fmaxf(sf[j][2], sf[j][3]));
        }
        mt0 = fmaxf(mt0, __shfl_xor_sync(0xffffffffu, mt0, 1));
        mt0 = fmaxf(mt0, __shfl_xor_sync(0xffffffffu, mt0, 2));
        mt1 = fmaxf(mt1, __shfl_xor_sync(0xffffffffu, mt1, 1));
        mt1 = fmaxf(mt1, __shfl_xor_sync(0xffffffffu, mt1, 2));
        float mn0 = fmaxf(m0, mt0), mn1 = fmaxf(m1, mt1);
        float f0 = fast_exp2(m0 - mn0), f1 = fast_exp2(m1 - mn1);
        m0 = mn0; m1 = mn1;
        float rs0 = 0.f, rs1 = 0.f;
#pragma unroll
        for (int j = 0; j < 16; j++) {
            sf[j][0] = fast_exp2(sf[j][0] - mn0);
            sf[j][1] = fast_exp2(sf[j][1] - mn0);
            sf[j][2] = fast_exp2(sf[j][2] - mn1);
            sf[j][3] = fast_exp2(sf[j][3] - mn1);
            rs0 += sf[j][0] + sf[j][1];
            rs1 += sf[j][2] + sf[j][3];
        }
        rs0 += __shfl_xor_sync(0xffffffffu, rs0, 1);
        rs0 += __shfl_xor_sync(0xffffffffu, rs0, 2);
        rs1 += __shfl_xor_sync(0xffffffffu, rs1, 1);
        rs1 += __shfl_xor_sync(0xffffffffu, rs1, 2);
        l0 = l0 * f0 + rs0;
        l1 = l1 * f1 + rs1;
#pragma unroll
        for (int j = 0; j < 8; j++) {
            of[j][0] *= f0; of[j][1] *= f0; of[j][2] *= f1; of[j][3] *= f1;
        }

        // ---- O += P V (single fp16 pass) ----
#pragma unroll
        for (int kp = 0; kp < 8; kp++) {
            u32 ah[4];
            ah[0] = cvt_f16x2(sf[2 * kp][0],     sf[2 * kp][1]);
            ah[1] = cvt_f16x2(sf[2 * kp][2],     sf[2 * kp][3]);
            ah[2] = cvt_f16x2(sf[2 * kp + 1][0], sf[2 * kp + 1][1]);
            ah[3] = cvt_f16x2(sf[2 * kp + 1][2], sf[2 * kp + 1][3]);
            u32 bv[4][4];
#pragma unroll
            for (int dt = 0; dt < 4; dt++) {
                u32 off = ((kp * 16 + vrow) * FA_RS + dt * 16 + vch * 8) * 2;
                ldsm_x4t(bv[dt][0], bv[dt][1], bv[dt][2], bv[dt][3],
                         stb + FA_ARR * 2 + off);
            }
#pragma unroll
            for (int dt = 0; dt < 4; dt++) {
                mma16816h(of[2 * dt],     ah, &bv[dt][0]);
                mma16816h(of[2 * dt + 1], ah, &bv[dt][2]);
            }
        }
        __syncthreads();
    }

    // ---- epilogue: normalize, store single fp16 ----
    float inv0 = 1.f / l0, inv1 = 1.f / l1;
    const int g = lane >> 2, t2 = (lane & 3) * 2;
    size_t r0 = rowbase + qt * 128 + w * 16 + g;
#pragma unroll
    for (int j = 0; j < 8; j++) {
        int c = colbase + j * 8 + t2;
        u32 v0 = cvt_f16x2(of[j][0] * inv0, of[j][1] * inv0);
        u32 v1 = cvt_f16x2(of[j][2] * inv1, of[j][3] * inv1);
        *(u32*)(o16 + r0 * C_DIM + c) = v0;
        *(u32*)(o16 + (r0 + 8) * C_DIM + c) = v1;
    }
#undef FA_LOAD
}

// ---------------------------------------------------------------------------
extern "C" void kernel_launch(void* const* d_in, const int* in_sizes, int n_in,
                              void* d_out, int out_size)
{
    const float* x     = (const float*)d_in[0];
    const float* Wqkv  = (const float*)d_in[1];
    const float* bqkv  = (const float*)d_in[2];
    const float* Wproj = (const float*)d_in[3];
    const float* bproj = (const float*)d_in[4];
    float* out = (float*)d_out;

    __half *q16, *k16, *v16, *xh16, *xl16, *o16, *wq16, *wp16;
    cudaGetSymbolAddress((void**)&q16, g_q16);
    cudaGetSymbolAddress((void**)&k16, g_k16);   cudaGetSymbolAddress((void**)&v16, g_v16);
    cudaGetSymbolAddress((void**)&xh16, g_xh16); cudaGetSymbolAddress((void**)&xl16, g_xl16);
    cudaGetSymbolAddress((void**)&o16, g_o16);
    cudaGetSymbolAddress((void**)&wq16, g_wq16); cudaGetSymbolAddress((void**)&wp16, g_wp16);

    const int SM_QKV  = 2 * 3 * ARR_B;   // NA=2: A0,A1,B x2 stages = 61440 B
    const int SM_PROJ = 2 * 2 * ARR_B;   // NA=1: A0,B  x2 stages = 40960 B
    cudaFuncSetAttribute((const void*)gemm_f16_kernel<2, 1, 1>,
                         cudaFuncAttributeMaxDynamicSharedMemorySize, SM_QKV);
    cudaFuncSetAttribute((const void*)gemm_f16_kernel<1, 0, 0>,
                         cudaFuncAttributeMaxDynamicSharedMemorySize, SM_PROJ);
    cudaFuncSetAttribute(flash_attn_mma,
                         cudaFuncAttributeMaxDynamicSharedMemorySize, FA_SMEM);

    // prep: x -> fp16 hi/lo; weights -> transposed single fp16
    split16_kernel<<<(M_ROWS * C_DIM / 4 + 255) / 256, 256>>>(
        x, xh16, xl16, M_ROWS * C_DIM / 4);
    transpose_f16_kernel<<<dim3(C3 / 32, C_DIM / 32), dim3(32, 8)>>>(
        Wqkv, wq16, C_DIM, C3);
    transpose_f16_kernel<<<dim3(C_DIM / 32, C_DIM / 32), dim3(32, 8)>>>(
        Wproj, wp16, C_DIM, C_DIM);

    // 1) qkv projection: q 2-pass (pre-scaled), k/v single-pass; interleaved blocks
    gemm_f16_kernel<2, 1, 1><<<dim3(C3 / 128, M_ROWS / 128), 128, SM_QKV>>>(
        xh16, xl16, wq16, bqkv, nullptr, M_ROWS, C3, C_DIM,
        q16, k16, v16);

    // 2) attention -> single fp16
    flash_attn_mma<<<dim3(T_SZ / 128, B_SZ * NH), 256, FA_SMEM>>>(
        q16, k16, v16, o16);

    // 3) out = attn @ Wproj + bproj (fp16 single-pass)
    gemm_f16_kernel<1, 0, 0><<<dim3(C_DIM / 128, M_ROWS / 128), 128, SM_PROJ>>>(
        o16, nullptr, wp16, bproj, out, M_ROWS, C_DIM, C_DIM,
        nullptr, nullptr, nullptr);
}

// round 16
// speedup vs baseline: 1.0356x; 1.0260x over previous
#include <cuda_runtime.h>
#include <cuda_bf16.h>
#include <cuda_fp16.h>
#include <math_constants.h>

#define C_DIM 1024
#define C3    3072
#define NH    16
#define HD    64
#define B_SZ  2
#define T_SZ  2048
#define M_ROWS (B_SZ*T_SZ)

#define ATT_SCALE 0.5f
#define LOG2E 1.4426950408889634f
#define QSC (ATT_SCALE * LOG2E)

typedef unsigned long long u64;
typedef unsigned int u32;

// ---------------- scratch (no device allocation allowed) -------------------
__device__ __half g_q16[(size_t)M_ROWS * C_DIM];    // Q fp16, pre-scaled by QSC
__device__ __half g_k16[(size_t)M_ROWS * C_DIM];    // K single fp16
__device__ __half g_v16[(size_t)M_ROWS * C_DIM];    // V single fp16
__device__ __half g_xh16[(size_t)M_ROWS * C_DIM];   // x fp16 hi
__device__ __half g_xl16[(size_t)M_ROWS * C_DIM];   // x fp16 lo
__device__ __half g_o16[(size_t)M_ROWS * C_DIM];    // attn out single fp16
__device__ __half g_wq16[(size_t)C3 * C_DIM];       // Wqkv^T single fp16 [N][K]
__device__ __half g_wp16[(size_t)C_DIM * C_DIM];    // Wproj^T single fp16

// ---------------- helpers ----------------------------------------------------
__device__ __forceinline__ u32 smem_u32(const void* p) {
    u32 a; asm("{ .reg .u64 t; cvta.to.shared.u64 t, %1; cvt.u32.u64 %0, t; }"
               : "=r"(a) : "l"(p));
    return a;
}
__device__ __forceinline__ void ldsm_x4(u32& r0, u32& r1, u32& r2, u32& r3, u32 a) {
    asm volatile("ldmatrix.sync.aligned.m8n8.x4.shared.b16 {%0,%1,%2,%3}, [%4];"
                 : "=r"(r0), "=r"(r1), "=r"(r2), "=r"(r3) : "r"(a));
}
__device__ __forceinline__ void ldsm_x4t(u32& r0, u32& r1, u32& r2, u32& r3, u32 a) {
    asm volatile("ldmatrix.sync.aligned.m8n8.x4.trans.shared.b16 {%0,%1,%2,%3}, [%4];"
                 : "=r"(r0), "=r"(r1), "=r"(r2), "=r"(r3) : "r"(a));
}
__device__ __forceinline__ void mma16816h(float* c, const u32* a, const u32* b) {
    asm volatile(
        "mma.sync.aligned.m16n8k16.row.col.f32.f16.f16.f32 "
        "{%0,%1,%2,%3},{%4,%5,%6,%7},{%8,%9},{%0,%1,%2,%3};"
        : "+f"(c[0]), "+f"(c[1]), "+f"(c[2]), "+f"(c[3])
        : "r"(a[0]), "r"(a[1]), "r"(a[2]), "r"(a[3]), "r"(b[0]), "r"(b[1]));
}
__device__ __forceinline__ float fast_exp2(float x) {
    float r; asm("ex2.approx.ftz.f32 %0, %1;" : "=f"(r) : "f"(x)); return r;
}
__device__ __forceinline__ u32 cvt_f16x2(float lo, float hi) {
    u32 r; asm("cvt.rn.f16x2.f32 %0, %1, %2;" : "=r"(r) : "f"(hi), "f"(lo));
    return r;
}
__device__ __forceinline__ void split2h(float f0, float f1, u32& hi, u32& lo) {
    hi = cvt_f16x2(f0, f1);
    __half2 h2 = *reinterpret_cast<__half2*>(&hi);
    float2 hf = __half22float2(h2);
    lo = cvt_f16x2(f0 - hf.x, f1 - hf.y);
}
#define CP_ASYNC16(d, s) asm volatile("cp.async.cg.shared.global [%0], [%1], 16;" :: "r"(d), "l"(s))
#define CP_COMMIT()      asm volatile("cp.async.commit_group;" ::: "memory")
#define CP_WAIT1()       asm volatile("cp.async.wait_group 1;" ::: "memory")
#define CP_WAIT0()       asm volatile("cp.async.wait_group 0;" ::: "memory")

// ---------------- prep: fp32 -> fp16 hi/lo split -----------------------------
__global__ void split16_kernel(const float* __restrict__ in,
                               __half* __restrict__ hi,
                               __half* __restrict__ lo, int n4)
{
    int i = blockIdx.x * blockDim.x + threadIdx.x;
    if (i >= n4) return;
    float4 v = ((const float4*)in)[i];
    u32 h0, l0, h1, l1;
    split2h(v.x, v.y, h0, l0);
    split2h(v.z, v.w, h1, l1);
    ((uint2*)hi)[i] = make_uint2(h0, h1);
    ((uint2*)lo)[i] = make_uint2(l0, l1);
}

// ---------------- prep: both weights -> W^T single fp16 [N][K], one launch --
// z = 0: Wqkv (N = C3).  z = 1: Wproj (N = C_DIM; only first 32 x-blocks).
__global__ void transpose_both_kernel(const float* __restrict__ Wq,
                                      const float* __restrict__ Wp,
                                      __half* __restrict__ Wq16,
                                      __half* __restrict__ Wp16)
{
    __shared__ float ts[32][33];
    const int z = blockIdx.z;
    const int N = z == 0 ? C3 : C_DIM;
    int n0 = blockIdx.x * 32;
    if (n0 >= N) return;
    int k0 = blockIdx.y * 32;
    const float* W = z == 0 ? Wq : Wp;
    __half* W16 = z == 0 ? Wq16 : Wp16;
    int tx = threadIdx.x, ty = threadIdx.y;  // 32 x 8
#pragma unroll
    for (int r = 0; r < 4; r++)
        ts[ty + 8 * r][tx] = W[(size_t)(k0 + ty + 8 * r) * N + n0 + tx];
    __syncthreads();
#pragma unroll
    for (int r = 0; r < 4; r++) {
        float v = ts[tx][ty + 8 * r];
        W16[(size_t)(n0 + ty + 8 * r) * C_DIM + k0 + tx] = __float2half_rn(v);
    }
}

// ---------------- fp16 GEMM: C = (A0 [+A1]) @ B16^T + bias ------------------
// NA=2 (QKV): A1 pass applied only for Q columns (n0 < C_DIM), natural order.
// EPI 0: fp32 C out.  EPI 1: q/k/v fp16 out by column part; Q pre-scaled QSC.
#define RSTRIDE 80
#define ARR_B   (128 * RSTRIDE)

extern __shared__ char sm_raw[];

template<int NA, int EPI>
__global__ void __launch_bounds__(128) gemm_f16_kernel(
    const __half* __restrict__ A0, const __half* __restrict__ A1,
    const __half* __restrict__ B16,
    const float* __restrict__ bias, float* __restrict__ C,
    int M, int N, int K,
    __half* oq16, __half* ok16, __half* ov16)
{
    const int STB = (NA + 1) * ARR_B;

    const int tid = threadIdx.x, lane = tid & 31, wid = tid >> 5;
    const int warp_m = wid & 1, warp_n = wid >> 1;
    const int m0 = blockIdx.y * 128, n0 = blockIdx.x * 128;

    // 2nd A pass only for Q columns; uniform per block.
    const bool useA1 = (NA == 2) && (n0 < C_DIM);

    const int grp = lane >> 3, lrow = lane & 7;
    const int a_row = (grp & 1) * 8 + lrow, a_kb = (grp >> 1) * 16;
    const int b_row = (grp >> 1) * 8 + lrow, b_kb = (grp & 1) * 16;

    float cf[4][8][4];
#pragma unroll
    for (int tm = 0; tm < 4; tm++)
#pragma unroll
        for (int tn = 0; tn < 8; tn++)
#pragma unroll
            for (int q = 0; q < 4; q++) cf[tm][tn][q] = 0.f;

#define G_LOAD(st, k0v)                                                         \
    do {                                                                        \
        char* _b = sm_raw + (st) * STB;                                         \
        _Pragma("unroll")                                                       \
        for (int j = 0; j < 4; j++) {                                           \
            int _i = tid + j * 128;                                             \
            int _r = _i >> 2, _c = _i & 3;                                      \
            u32 _d0 = smem_u32(_b + _r * RSTRIDE + _c * 16);                    \
            CP_ASYNC16(_d0, A0 + (size_t)(m0 + _r) * K + (k0v) + _c * 8);       \
            u32 _db = smem_u32(_b + NA * ARR_B + _r * RSTRIDE + _c * 16);       \
            CP_ASYNC16(_db, B16 + (size_t)(n0 + _r) * K + (k0v) + _c * 8);      \
            if (useA1) {                                                        \
                u32 _d1 = smem_u32(_b + ARR_B + _r * RSTRIDE + _c * 16);        \
                CP_ASYNC16(_d1, A1 + (size_t)(m0 + _r) * K + (k0v) + _c * 8);   \
            }                                                                   \
        }                                                                       \
    } while (0)

#define G_COMPUTE(st)                                                           \
    do {                                                                        \
        u32 _sb = smem_u32(sm_raw) + (st) * STB;                                \
        _Pragma("unroll")                                                       \
        for (int ks = 0; ks < 2; ks++) {                                        \
            u32 afr0[4][4], bfr[4][4];                                          \
            _Pragma("unroll")                                                   \
            for (int tm = 0; tm < 4; tm++)                                      \
                ldsm_x4(afr0[tm][0], afr0[tm][1], afr0[tm][2], afr0[tm][3],     \
                        _sb + (warp_m * 64 + tm * 16 + a_row) * RSTRIDE +       \
                        ks * 32 + a_kb);                                        \
            _Pragma("unroll")                                                   \
            for (int t2 = 0; t2 < 4; t2++)                                      \
                ldsm_x4(bfr[t2][0], bfr[t2][1], bfr[t2][2], bfr[t2][3],         \
                        _sb + NA * ARR_B +                                      \
                        (warp_n * 64 + t2 * 16 + b_row) * RSTRIDE +             \
                        ks * 32 + b_kb);                                        \
            _Pragma("unroll")                                                   \
            for (int tm = 0; tm < 4; tm++)                                      \
                _Pragma("unroll")                                               \
                for (int tn = 0; tn < 8; tn++)                                  \
                    mma16816h(cf[tm][tn], afr0[tm],                             \
                              &bfr[tn >> 1][(tn & 1) * 2]);                     \
            if (useA1) {                                                        \
                u32 afr1[4][4];                                                 \
                _Pragma("unroll")                                               \
                for (int tm = 0; tm < 4; tm++)                                  \
                    ldsm_x4(afr1[tm][0], afr1[tm][1], afr1[tm][2], afr1[tm][3], \
                            _sb + ARR_B +                                       \
                            (warp_m * 64 + tm * 16 + a_row) * RSTRIDE +         \
                            ks * 32 + a_kb);                                    \
                _Pragma("unroll")                                               \
                for (int tm = 0; tm < 4; tm++)                                  \
                    _Pragma("unroll")                                           \
                    for (int tn = 0; tn < 8; tn++)                              \
                        mma16816h(cf[tm][tn], afr1[tm],                         \
                                  &bfr[tn >> 1][(tn & 1) * 2]);                 \
            }                                                                   \
        }                                                                       \
    } while (0)

    const int NIT = K / 32;
    G_LOAD(0, 0);
    CP_COMMIT();
    for (int it = 0; it < NIT; it++) {
        if (it + 1 < NIT) {
            G_LOAD((it + 1) & 1, (it + 1) * 32);
            CP_COMMIT();
            CP_WAIT1();
        } else {
            CP_WAIT0();
        }
        __syncthreads();
        G_COMPUTE(it & 1);
        __syncthreads();
    }

    const int mrow = lane >> 2, ncol = (lane & 3) * 2;
    if (EPI == 0) {
#pragma unroll
        for (int tm = 0; tm < 4; tm++)
#pragma unroll
            for (int tn = 0; tn < 8; tn++) {
                int r = m0 + warp_m * 64 + tm * 16 + mrow;
                int c = n0 + warp_n * 64 + tn * 8 + ncol;
                float2 bb = *(const float2*)&bias[c];
                *(float2*)&C[(size_t)r * N + c] =
                    make_float2(cf[tm][tn][0] + bb.x, cf[tm][tn][1] + bb.y);
                *(float2*)&C[(size_t)(r + 8) * N + c] =
                    make_float2(cf[tm][tn][2] + bb.x, cf[tm][tn][3] + bb.y);
            }
    } else {
        int part = n0 >> 10;
        __half* dst = part == 0 ? oq16 : (part == 1 ? ok16 : ov16);
        float sc = part == 0 ? QSC : 1.0f;
#pragma unroll
        for (int tm = 0; tm < 4; tm++)
#pragma unroll
            for (int tn = 0; tn < 8; tn++) {
                int r = m0 + warp_m * 64 + tm * 16 + mrow;
                int c = n0 + warp_n * 64 + tn * 8 + ncol;
                int lc = c & 1023;
                float2 bb = *(const float2*)&bias[c];
                u32 v0 = cvt_f16x2((cf[tm][tn][0] + bb.x) * sc,
                                   (cf[tm][tn][1] + bb.y) * sc);
                u32 v1 = cvt_f16x2((cf[tm][tn][2] + bb.x) * sc,
                                   (cf[tm][tn][3] + bb.y) * sc);
                *(u32*)(dst + (size_t)r * C_DIM + lc) = v0;
                *(u32*)(dst + (size_t)(r + 8) * C_DIM + lc) = v1;
            }
    }
#undef G_LOAD
#undef G_COMPUTE
}

// ---------------- tensor-core flash attention -------------------------------
// S = Qs @ K16^T (Q pre-scaled -> logits already exp2-domain). PV = P16 @ V16.
#define FA_RS   72
#define FA_ARR  (128 * FA_RS)
#define FA_ST0  FA_ARR
#define FA_STSZ (2 * FA_ARR)
#define FA_SMEM ((FA_ARR + 2 * FA_STSZ) * 2)   // 92160 B -> 2 CTAs/SM

__global__ void __launch_bounds__(256) flash_attn_mma(
    const __half* __restrict__ q16, const __half* __restrict__ k16,
    const __half* __restrict__ v16, __half* __restrict__ o16)
{
    __half* sm = (__half*)sm_raw;
    const int tid = threadIdx.x, lane = tid & 31, w = tid >> 5;
    const int qt = blockIdx.x;
    const int b = blockIdx.y >> 4, h = blockIdx.y & 15;
    const size_t rowbase = (size_t)b * T_SZ;
    const int colbase = h * HD;

    const __half* kvsrc[2] = {k16, v16};

#define FA_LOAD(st, kt)                                                         \
    do {                                                                        \
        _Pragma("unroll")                                                       \
        for (int a4 = 0; a4 < 2; a4++) {                                        \
            _Pragma("unroll")                                                   \
            for (int j = 0; j < 4; j++) {                                       \
                int idx = tid + j * 256;                                        \
                int r = idx >> 3, c8 = idx & 7;                                 \
                u32 d = smem_u32(sm + FA_ST0 + (st) * FA_STSZ + a4 * FA_ARR +   \
                                 r * FA_RS + c8 * 8);                           \
                CP_ASYNC16(d, kvsrc[a4] +                                       \
                           (rowbase + (kt) * 128 + r) * C_DIM + colbase + c8 * 8); \
            }                                                                   \
        }                                                                       \
    } while (0)

    FA_LOAD(0, 0);
    CP_COMMIT();

    // stage Q (pre-scaled fp16)
#pragma unroll
    for (int j = 0; j < 4; j++) {
        int idx = tid + j * 256;
        int r = idx >> 3, c8 = idx & 7;
        uint4 v = *(const uint4*)(q16 +
            (rowbase + qt * 128 + r) * C_DIM + colbase + c8 * 8);
        *(uint4*)(sm + r * FA_RS + c8 * 8) = v;
    }
    __syncthreads();

    u32 qf[4][4];
    {
        u32 qbase = smem_u32(sm);
        int arow = w * 16 + (lane & 15);
        int acol = (lane >> 4) * 8;
#pragma unroll
        for (int ks = 0; ks < 4; ks++) {
            u32 off = (arow * FA_RS + ks * 16 + acol) * 2;
            ldsm_x4(qf[ks][0], qf[ks][1], qf[ks][2], qf[ks][3], qbase + off);
        }
    }

    float sf[16][4];
    float of[8][4];
#pragma unroll
    for (int j = 0; j < 8; j++)
#pragma unroll
        for (int q = 0; q < 4; q++) of[j][q] = 0.f;
    float m0 = -CUDART_INF_F, m1 = -CUDART_INF_F, l0 = 0.f, l1 = 0.f;

    const u32 sbase = smem_u32(sm);
    const int krow = (lane & 7) + ((lane >> 4) << 3);
    const int kch  = (lane >> 3) & 1;
    const int vrow = (lane & 7) + (((lane >> 3) & 1) << 3);
    const int vch  = lane >> 4;

    for (int kt = 0; kt < T_SZ / 128; kt++) {
        if (kt + 1 < T_SZ / 128) { FA_LOAD((kt + 1) & 1, kt + 1); CP_COMMIT(); CP_WAIT1(); }
        else CP_WAIT0();
        __syncthreads();
        u32 stb = sbase + (FA_ST0 + (kt & 1) * FA_STSZ) * 2;

        // ---- S = Qs K^T (single fp16 pass, exp2-domain logits) ----
#pragma unroll
        for (int j = 0; j < 16; j++) {
            sf[j][0] = 0.f; sf[j][1] = 0.f; sf[j][2] = 0.f; sf[j][3] = 0.f;
        }
#pragma unroll
        for (int jp = 0; jp < 4; jp++) {
            u32 bh[2][4][4];
#pragma unroll
            for (int j2 = 0; j2 < 2; j2++)
#pragma unroll
                for (int ks = 0; ks < 4; ks++) {
                    u32 off = (((jp * 2 + j2) * 16 + krow) * FA_RS +
                               ks * 16 + kch * 8) * 2;
                    ldsm_x4(bh[j2][ks][0], bh[j2][ks][1], bh[j2][ks][2], bh[j2][ks][3],
                            stb + off);
                }
            float* s0 = sf[4 * jp];     float* s1 = sf[4 * jp + 1];
            float* s2 = sf[4 * jp + 2]; float* s3 = sf[4 * jp + 3];
#pragma unroll
            for (int ks = 0; ks < 4; ks++) {
                mma16816h(s0, qf[ks], &bh[0][ks][0]);
                mma16816h(s1, qf[ks], &bh[0][ks][2]);
                mma16816h(s2, qf[ks], &bh[1][ks][0]);
                mma16816h(s3, qf[ks], &bh[1][ks][2]);
            }
        }

        // ---- online softmax (logits already exp2-domain) ----
        float mt0 = -CUDART_INF_F, mt1 = -CUDART_INF_F;
#pragma unroll
        for (int j = 0; j < 16; j++) {
            mt0 = fmaxf(mt0, fmaxf(sf[j][0], sf[j][1]));
            mt1 = fmaxf(mt1, fmaxf(sf[j][2], sf[j][3]));
        }
        mt0 = fmaxf(mt0, __shfl_xor_sync(0xffffffffu, mt0, 1));
        mt0 = fmaxf(mt0, __shfl_xor_sync(0xffffffffu, mt0, 2));
        mt1 = fmaxf(mt1, __shfl_xor_sync(0xffffffffu, mt1, 1));
        mt1 = fmaxf(mt1, __shfl_xor_sync(0xffffffffu, mt1, 2));
        float mn0 = fmaxf(m0, mt0), mn1 = fmaxf(m1, mt1);
        float f0 = fast_exp2(m0 - mn0), f1 = fast_exp2(m1 - mn1);
        m0 = mn0; m1 = mn1;
        float rs0 = 0.f, rs1 = 0.f;
#pragma unroll
        for (int j = 0; j < 16; j++) {
            sf[j][0] = fast_exp2(sf[j][0] - mn0);
            sf[j][1] = fast_exp2(sf[j][1] - mn0);
            sf[j][2] = fast_exp2(sf[j][2] - mn1);
            sf[j][3] = fast_exp2(sf[j][3] - mn1);
            rs0 += sf[j][0] + sf[j][1];
            rs1 += sf[j][2] + sf[j][3];
        }
        rs0 += __shfl_xor_sync(0xffffffffu, rs0, 1);
        rs0 += __shfl_xor_sync(0xffffffffu, rs0, 2);
        rs1 += __shfl_xor_sync(0xffffffffu, rs1, 1);
        rs1 += __shfl_xor_sync(0xffffffffu, rs1, 2);
        l0 = l0 * f0 + rs0;
        l1 = l1 * f1 + rs1;
#pragma unroll
        for (int j = 0; j < 8; j++) {
            of[j][0] *= f0; of[j][1] *= f0; of[j][2] *= f1; of[j][3] *= f1;
        }

        // ---- O += P V (single fp16 pass) ----
#pragma unroll
        for (int kp = 0; kp < 8; kp++) {
            u32 ah[4];
            ah[0] = cvt_f16x2(sf[2 * kp][0],     sf[2 * kp][1]);
            ah[1] = cvt_f16x2(sf[2 * kp][2],     sf[2 * kp][3]);
            ah[2] = cvt_f16x2(sf[2 * kp + 1][0], sf[2 * kp + 1][1]);
            ah[3] = cvt_f16x2(sf[2 * kp + 1][2], sf[2 * kp + 1][3]);
            u32 bv[4][4];
#pragma unroll
            for (int dt = 0; dt < 4; dt++) {
                u32 off = ((kp * 16 + vrow) * FA_RS + dt * 16 + vch * 8) * 2;
                ldsm_x4t(bv[dt][0], bv[dt][1], bv[dt][2], bv[dt][3],
                         stb + FA_ARR * 2 + off);
            }
#pragma unroll
            for (int dt = 0; dt < 4; dt++) {
                mma16816h(of[2 * dt],     ah, &bv[dt][0]);
                mma16816h(of[2 * dt + 1], ah, &bv[dt][2]);
            }
        }
        __syncthreads();
    }

    // ---- epilogue: normalize, store single fp16 ----
    float inv0 = 1.f / l0, inv1 = 1.f / l1;
    const int g = lane >> 2, t2 = (lane & 3) * 2;
    size_t r0 = rowbase + qt * 128 + w * 16 + g;
#pragma unroll
    for (int j = 0; j < 8; j++) {
        int c = colbase + j * 8 + t2;
        u32 v0 = cvt_f16x2(of[j][0] * inv0, of[j][1] * inv0);
        u32 v1 = cvt_f16x2(of[j][2] * inv1, of[j][3] * inv1);
        *(u32*)(o16 + r0 * C_DIM + c) = v0;
        *(u32*)(o16 + (r0 + 8) * C_DIM + c) = v1;
    }
#undef FA_LOAD
}

// ---------------------------------------------------------------------------
extern "C" void kernel_launch(void* const* d_in, const int* in_sizes, int n_in,
                              void* d_out, int out_size)
{
    const float* x     = (const float*)d_in[0];
    const float* Wqkv  = (const float*)d_in[1];
    const float* bqkv  = (const float*)d_in[2];
    const float* Wproj = (const float*)d_in[3];
    const float* bproj = (const float*)d_in[4];
    float* out = (float*)d_out;

    __half *q16, *k16, *v16, *xh16, *xl16, *o16, *wq16, *wp16;
    cudaGetSymbolAddress((void**)&q16, g_q16);
    cudaGetSymbolAddress((void**)&k16, g_k16);   cudaGetSymbolAddress((void**)&v16, g_v16);
    cudaGetSymbolAddress((void**)&xh16, g_xh16); cudaGetSymbolAddress((void**)&xl16, g_xl16);
    cudaGetSymbolAddress((void**)&o16, g_o16);
    cudaGetSymbolAddress((void**)&wq16, g_wq16); cudaGetSymbolAddress((void**)&wp16, g_wp16);

    const int SM_QKV  = 2 * 3 * ARR_B;   // NA=2: A0,A1,B x2 stages = 61440 B
    const int SM_PROJ = 2 * 2 * ARR_B;   // NA=1: A0,B  x2 stages = 40960 B
    cudaFuncSetAttribute((const void*)gemm_f16_kernel<2, 1>,
                         cudaFuncAttributeMaxDynamicSharedMemorySize, SM_QKV);
    cudaFuncSetAttribute((const void*)gemm_f16_kernel<1, 0>,
                         cudaFuncAttributeMaxDynamicSharedMemorySize, SM_PROJ);
    cudaFuncSetAttribute(flash_attn_mma,
                         cudaFuncAttributeMaxDynamicSharedMemorySize, FA_SMEM);

    // prep: x -> fp16 hi/lo; both weights transposed in ONE launch
    split16_kernel<<<(M_ROWS * C_DIM / 4 + 255) / 256, 256>>>(
        x, xh16, xl16, M_ROWS * C_DIM / 4);
    transpose_both_kernel<<<dim3(C3 / 32, C_DIM / 32, 2), dim3(32, 8)>>>(
        Wqkv, Wproj, wq16, wp16);

    // 1) qkv projection: q 2-pass (pre-scaled by QSC), k/v single-pass
    gemm_f16_kernel<2, 1><<<dim3(C3 / 128, M_ROWS / 128), 128, SM_QKV>>>(
        xh16, xl16, wq16, bqkv, nullptr, M_ROWS, C3, C_DIM,
        q16, k16, v16);

    // 2) attention -> single fp16
    flash_attn_mma<<<dim3(T_SZ / 128, B_SZ * NH), 256, FA_SMEM>>>(
        q16, k16, v16, o16);

    // 3) out = attn @ Wproj + bproj (fp16 single-pass)
    gemm_f16_kernel<1, 0><<<dim3(C_DIM / 128, M_ROWS / 128), 128, SM_PROJ>>>(
        o16, nullptr, wp16, bproj, out, M_ROWS, C_DIM, C_DIM,
        nullptr, nullptr, nullptr);
}

// round 17
// speedup vs baseline: 1.0915x; 1.0539x over previous
#include <cuda_runtime.h>
#include <cuda_bf16.h>
#include <cuda_fp16.h>
#include <math_constants.h>

#define C_DIM 1024
#define C3    3072
#define NH    16
#define HD    64
#define B_SZ  2
#define T_SZ  2048
#define M_ROWS (B_SZ*T_SZ)

#define ATT_SCALE 0.5f
#define LOG2E 1.4426950408889634f
#define QSC (ATT_SCALE * LOG2E)

typedef unsigned long long u64;
typedef unsigned int u32;

// ---------------- scratch (no device allocation allowed) -------------------
__device__ __half g_q16[(size_t)M_ROWS * C_DIM];    // Q fp16, pre-scaled by QSC
__device__ __half g_k16[(size_t)M_ROWS * C_DIM];    // K single fp16
__device__ __half g_v16[(size_t)M_ROWS * C_DIM];    // V single fp16
__device__ __half g_xh16[(size_t)M_ROWS * C_DIM];   // x fp16 hi
__device__ __half g_xl16[(size_t)M_ROWS * C_DIM];   // x fp16 lo
__device__ __half g_o16[(size_t)M_ROWS * C_DIM];    // attn out single fp16
__device__ __half g_wq16[(size_t)C3 * C_DIM];       // Wqkv^T single fp16 [N][K]
__device__ __half g_wp16[(size_t)C_DIM * C_DIM];    // Wproj^T single fp16

// ---------------- helpers ----------------------------------------------------
__device__ __forceinline__ u32 smem_u32(const void* p) {
    u32 a; asm("{ .reg .u64 t; cvta.to.shared.u64 t, %1; cvt.u32.u64 %0, t; }"
               : "=r"(a) : "l"(p));
    return a;
}
__device__ __forceinline__ void ldsm_x4(u32& r0, u32& r1, u32& r2, u32& r3, u32 a) {
    asm volatile("ldmatrix.sync.aligned.m8n8.x4.shared.b16 {%0,%1,%2,%3}, [%4];"
                 : "=r"(r0), "=r"(r1), "=r"(r2), "=r"(r3) : "r"(a));
}
__device__ __forceinline__ void ldsm_x4t(u32& r0, u32& r1, u32& r2, u32& r3, u32 a) {
    asm volatile("ldmatrix.sync.aligned.m8n8.x4.trans.shared.b16 {%0,%1,%2,%3}, [%4];"
                 : "=r"(r0), "=r"(r1), "=r"(r2), "=r"(r3) : "r"(a));
}
__device__ __forceinline__ void mma16816h(float* c, const u32* a, const u32* b) {
    asm volatile(
        "mma.sync.aligned.m16n8k16.row.col.f32.f16.f16.f32 "
        "{%0,%1,%2,%3},{%4,%5,%6,%7},{%8,%9},{%0,%1,%2,%3};"
        : "+f"(c[0]), "+f"(c[1]), "+f"(c[2]), "+f"(c[3])
        : "r"(a[0]), "r"(a[1]), "r"(a[2]), "r"(a[3]), "r"(b[0]), "r"(b[1]));
}
__device__ __forceinline__ float fast_exp2(float x) {
    float r; asm("ex2.approx.ftz.f32 %0, %1;" : "=f"(r) : "f"(x)); return r;
}
__device__ __forceinline__ u32 cvt_f16x2(float lo, float hi) {
    u32 r; asm("cvt.rn.f16x2.f32 %0, %1, %2;" : "=r"(r) : "f"(hi), "f"(lo));
    return r;
}
__device__ __forceinline__ void split2h(float f0, float f1, u32& hi, u32& lo) {
    hi = cvt_f16x2(f0, f1);
    __half2 h2 = *reinterpret_cast<__half2*>(&hi);
    float2 hf = __half22float2(h2);
    lo = cvt_f16x2(f0 - hf.x, f1 - hf.y);
}
#define CP_ASYNC16(d, s) asm volatile("cp.async.cg.shared.global [%0], [%1], 16;" :: "r"(d), "l"(s))
#define CP_COMMIT()      asm volatile("cp.async.commit_group;" ::: "memory")
#define CP_WAIT1()       asm volatile("cp.async.wait_group 1;" ::: "memory")
#define CP_WAIT0()       asm volatile("cp.async.wait_group 0;" ::: "memory")

// ---------------- prep: fp32 -> fp16 hi/lo split -----------------------------
__global__ void split16_kernel(const float* __restrict__ in,
                               __half* __restrict__ hi,
                               __half* __restrict__ lo, int n4)
{
    int i = blockIdx.x * blockDim.x + threadIdx.x;
    if (i >= n4) return;
    float4 v = ((const float4*)in)[i];
    u32 h0, l0, h1, l1;
    split2h(v.x, v.y, h0, l0);
    split2h(v.z, v.w, h1, l1);
    ((uint2*)hi)[i] = make_uint2(h0, h1);
    ((uint2*)lo)[i] = make_uint2(l0, l1);
}

// ---------------- prep: both weights -> W^T single fp16 [N][K], one launch --
__global__ void transpose_both_kernel(const float* __restrict__ Wq,
                                      const float* __restrict__ Wp,
                                      __half* __restrict__ Wq16,
                                      __half* __restrict__ Wp16)
{
    __shared__ float ts[32][33];
    const int z = blockIdx.z;
    const int N = z == 0 ? C3 : C_DIM;
    int n0 = blockIdx.x * 32;
    if (n0 >= N) return;
    int k0 = blockIdx.y * 32;
    const float* W = z == 0 ? Wq : Wp;
    __half* W16 = z == 0 ? Wq16 : Wp16;
    int tx = threadIdx.x, ty = threadIdx.y;  // 32 x 8
#pragma unroll
    for (int r = 0; r < 4; r++)
        ts[ty + 8 * r][tx] = W[(size_t)(k0 + ty + 8 * r) * N + n0 + tx];
    __syncthreads();
#pragma unroll
    for (int r = 0; r < 4; r++) {
        float v = ts[tx][ty + 8 * r];
        W16[(size_t)(n0 + ty + 8 * r) * C_DIM + k0 + tx] = __float2half_rn(v);
    }
}

// ---------------- fp16 GEMM: C = (A0 [+A1]) @ B16^T + bias ------------------
// NA=2 (QKV): A1 pass only for Q columns (n0 < C_DIM), natural block order.
// EPI 0: fp32 C out.  EPI 1: q/k/v fp16 out by column part; Q pre-scaled QSC.
#define RSTRIDE 80
#define ARR_B   (128 * RSTRIDE)

extern __shared__ char sm_raw[];

template<int NA, int EPI>
__global__ void __launch_bounds__(128) gemm_f16_kernel(
    const __half* __restrict__ A0, const __half* __restrict__ A1,
    const __half* __restrict__ B16,
    const float* __restrict__ bias, float* __restrict__ C,
    int M, int N, int K,
    __half* oq16, __half* ok16, __half* ov16)
{
    const int STB = (NA + 1) * ARR_B;

    const int tid = threadIdx.x, lane = tid & 31, wid = tid >> 5;
    const int warp_m = wid & 1, warp_n = wid >> 1;
    const int m0 = blockIdx.y * 128, n0 = blockIdx.x * 128;

    const bool useA1 = (NA == 2) && (n0 < C_DIM);

    const int grp = lane >> 3, lrow = lane & 7;
    const int a_row = (grp & 1) * 8 + lrow, a_kb = (grp >> 1) * 16;
    const int b_row = (grp >> 1) * 8 + lrow, b_kb = (grp & 1) * 16;

    float cf[4][8][4];
#pragma unroll
    for (int tm = 0; tm < 4; tm++)
#pragma unroll
        for (int tn = 0; tn < 8; tn++)
#pragma unroll
            for (int q = 0; q < 4; q++) cf[tm][tn][q] = 0.f;

#define G_LOAD(st, k0v)                                                         \
    do {                                                                        \
        char* _b = sm_raw + (st) * STB;                                         \
        _Pragma("unroll")                                                       \
        for (int j = 0; j < 4; j++) {                                           \
            int _i = tid + j * 128;                                             \
            int _r = _i >> 2, _c = _i & 3;                                      \
            u32 _d0 = smem_u32(_b + _r * RSTRIDE + _c * 16);                    \
            CP_ASYNC16(_d0, A0 + (size_t)(m0 + _r) * K + (k0v) + _c * 8);       \
            u32 _db = smem_u32(_b + NA * ARR_B + _r * RSTRIDE + _c * 16);       \
            CP_ASYNC16(_db, B16 + (size_t)(n0 + _r) * K + (k0v) + _c * 8);      \
            if (useA1) {                                                        \
                u32 _d1 = smem_u32(_b + ARR_B + _r * RSTRIDE + _c * 16);        \
                CP_ASYNC16(_d1, A1 + (size_t)(m0 + _r) * K + (k0v) + _c * 8);   \
            }                                                                   \
        }                                                                       \
    } while (0)

#define G_COMPUTE(st)                                                           \
    do {                                                                        \
        u32 _sb = smem_u32(sm_raw) + (st) * STB;                                \
        _Pragma("unroll")                                                       \
        for (int ks = 0; ks < 2; ks++) {                                        \
            u32 afr0[4][4], bfr[4][4];                                          \
            _Pragma("unroll")                                                   \
            for (int tm = 0; tm < 4; tm++)                                      \
                ldsm_x4(afr0[tm][0], afr0[tm][1], afr0[tm][2], afr0[tm][3],     \
                        _sb + (warp_m * 64 + tm * 16 + a_row) * RSTRIDE +       \
                        ks * 32 + a_kb);                                        \
            _Pragma("unroll")                                                   \
            for (int t2 = 0; t2 < 4; t2++)                                      \
                ldsm_x4(bfr[t2][0], bfr[t2][1], bfr[t2][2], bfr[t2][3],         \
                        _sb + NA * ARR_B +                                      \
                        (warp_n * 64 + t2 * 16 + b_row) * RSTRIDE +             \
                        ks * 32 + b_kb);                                        \
            _Pragma("unroll")                                                   \
            for (int tm = 0; tm < 4; tm++)                                      \
                _Pragma("unroll")                                               \
                for (int tn = 0; tn < 8; tn++)                                  \
                    mma16816h(cf[tm][tn], afr0[tm],                             \
                              &bfr[tn >> 1][(tn & 1) * 2]);                     \
            if (useA1) {                                                        \
                u32 afr1[4][4];                                                 \
                _Pragma("unroll")                                               \
                for (int tm = 0; tm < 4; tm++)                                  \
                    ldsm_x4(afr1[tm][0], afr1[tm][1], afr1[tm][2], afr1[tm][3], \
                            _sb + ARR_B +                                       \
                            (warp_m * 64 + tm * 16 + a_row) * RSTRIDE +         \
                            ks * 32 + a_kb);                                    \
                _Pragma("unroll")                                               \
                for (int tm = 0; tm < 4; tm++)                                  \
                    _Pragma("unroll")                                           \
                    for (int tn = 0; tn < 8; tn++)                              \
                        mma16816h(cf[tm][tn], afr1[tm],                         \
                                  &bfr[tn >> 1][(tn & 1) * 2]);                 \
            }                                                                   \
        }                                                                       \
    } while (0)

    const int NIT = K / 32;
    G_LOAD(0, 0);
    CP_COMMIT();
    for (int it = 0; it < NIT; it++) {
        if (it + 1 < NIT) {
            G_LOAD((it + 1) & 1, (it + 1) * 32);
            CP_COMMIT();
            CP_WAIT1();
        } else {
            CP_WAIT0();
        }
        __syncthreads();
        G_COMPUTE(it & 1);
        __syncthreads();
    }

    const int mrow = lane >> 2, ncol = (lane & 3) * 2;
    if (EPI == 0) {
#pragma unroll
        for (int tm = 0; tm < 4; tm++)
#pragma unroll
            for (int tn = 0; tn < 8; tn++) {
                int r = m0 + warp_m * 64 + tm * 16 + mrow;
                int c = n0 + warp_n * 64 + tn * 8 + ncol;
                float2 bb = *(const float2*)&bias[c];
                *(float2*)&C[(size_t)r * N + c] =
                    make_float2(cf[tm][tn][0] + bb.x, cf[tm][tn][1] + bb.y);
                *(float2*)&C[(size_t)(r + 8) * N + c] =
                    make_float2(cf[tm][tn][2] + bb.x, cf[tm][tn][3] + bb.y);
            }
    } else {
        int part = n0 >> 10;
        __half* dst = part == 0 ? oq16 : (part == 1 ? ok16 : ov16);
        float sc = part == 0 ? QSC : 1.0f;
#pragma unroll
        for (int tm = 0; tm < 4; tm++)
#pragma unroll
            for (int tn = 0; tn < 8; tn++) {
                int r = m0 + warp_m * 64 + tm * 16 + mrow;
                int c = n0 + warp_n * 64 + tn * 8 + ncol;
                int lc = c & 1023;
                float2 bb = *(const float2*)&bias[c];
                u32 v0 = cvt_f16x2((cf[tm][tn][0] + bb.x) * sc,
                                   (cf[tm][tn][1] + bb.y) * sc);
                u32 v1 = cvt_f16x2((cf[tm][tn][2] + bb.x) * sc,
                                   (cf[tm][tn][3] + bb.y) * sc);
                *(u32*)(dst + (size_t)r * C_DIM + lc) = v0;
                *(u32*)(dst + (size_t)(r + 8) * C_DIM + lc) = v1;
            }
    }
#undef G_LOAD
#undef G_COMPUTE
}

// ---------------- tensor-core flash attention -------------------------------
// 128 threads / 4 warps, Q tile 64 rows (warp w owns rows w*16..w*16+15),
// KV tile 128 rows double-buffered. 2 CTAs/SM by registers (22K/CTA).
// S = Qs @ K16^T (Q pre-scaled -> logits exp2-domain). PV = P16 @ V16.
#define FA_RS   72
#define FA_KVARR (128 * FA_RS)               // one K or V array (elems)
#define FA_QARR  (64 * FA_RS)                // Q array (elems)
#define FA_ST0   FA_QARR
#define FA_STSZ  (2 * FA_KVARR)              // K16, V16 per stage
#define FA_SMEM  ((FA_QARR + 2 * FA_STSZ) * 2)   // 82944 B -> 2 CTAs/SM

__global__ void __launch_bounds__(128) flash_attn_mma(
    const __half* __restrict__ q16, const __half* __restrict__ k16,
    const __half* __restrict__ v16, __half* __restrict__ o16)
{
    __half* sm = (__half*)sm_raw;
    const int tid = threadIdx.x, lane = tid & 31, w = tid >> 5;
    const int qt = blockIdx.x;                 // 64-row q tile index
    const int b = blockIdx.y >> 4, h = blockIdx.y & 15;
    const size_t rowbase = (size_t)b * T_SZ;
    const int colbase = h * HD;

    const __half* kvsrc[2] = {k16, v16};

#define FA_LOAD(st, kt)                                                         \
    do {                                                                        \
        _Pragma("unroll")                                                       \
        for (int a4 = 0; a4 < 2; a4++) {                                        \
            _Pragma("unroll")                                                   \
            for (int j = 0; j < 8; j++) {                                       \
                int idx = tid + j * 128;                                        \
                int r = idx >> 3, c8 = idx & 7;                                 \
                u32 d = smem_u32(sm + FA_ST0 + (st) * FA_STSZ + a4 * FA_KVARR + \
                                 r * FA_RS + c8 * 8);                           \
                CP_ASYNC16(d, kvsrc[a4] +                                       \
                           (rowbase + (kt) * 128 + r) * C_DIM + colbase + c8 * 8); \
            }                                                                   \
        }                                                                       \
    } while (0)

    FA_LOAD(0, 0);
    CP_COMMIT();

    // stage Q (pre-scaled fp16): 64 rows x 64 cols
#pragma unroll
    for (int j = 0; j < 4; j++) {
        int idx = tid + j * 128;
        int r = idx >> 3, c8 = idx & 7;
        uint4 v = *(const uint4*)(q16 +
            (rowbase + qt * 64 + r) * C_DIM + colbase + c8 * 8);
        *(uint4*)(sm + r * FA_RS + c8 * 8) = v;
    }
    __syncthreads();

    u32 qf[4][4];
    {
        u32 qbase = smem_u32(sm);
        int arow = w * 16 + (lane & 15);
        int acol = (lane >> 4) * 8;
#pragma unroll
        for (int ks = 0; ks < 4; ks++) {
            u32 off = (arow * FA_RS + ks * 16 + acol) * 2;
            ldsm_x4(qf[ks][0], qf[ks][1], qf[ks][2], qf[ks][3], qbase + off);
        }
    }

    float sf[16][4];
    float of[8][4];
#pragma unroll
    for (int j = 0; j < 8; j++)
#pragma unroll
        for (int q = 0; q < 4; q++) of[j][q] = 0.f;
    float m0 = -CUDART_INF_F, m1 = -CUDART_INF_F, l0 = 0.f, l1 = 0.f;

    const u32 sbase = smem_u32(sm);
    const int krow = (lane & 7) + ((lane >> 4) << 3);
    const int kch  = (lane >> 3) & 1;
    const int vrow = (lane & 7) + (((lane >> 3) & 1) << 3);
    const int vch  = lane >> 4;

    for (int kt = 0; kt < T_SZ / 128; kt++) {
        if (kt + 1 < T_SZ / 128) { FA_LOAD((kt + 1) & 1, kt + 1); CP_COMMIT(); CP_WAIT1(); }
        else CP_WAIT0();
        __syncthreads();
        u32 stb = sbase + (FA_ST0 + (kt & 1) * FA_STSZ) * 2;

        // ---- S = Qs K^T (single fp16 pass, exp2-domain logits) ----
#pragma unroll
        for (int j = 0; j < 16; j++) {
            sf[j][0] = 0.f; sf[j][1] = 0.f; sf[j][2] = 0.f; sf[j][3] = 0.f;
        }
#pragma unroll
        for (int jp = 0; jp < 4; jp++) {
            u32 bh[2][4][4];
#pragma unroll
            for (int j2 = 0; j2 < 2; j2++)
#pragma unroll
                for (int ks = 0; ks < 4; ks++) {
                    u32 off = (((jp * 2 + j2) * 16 + krow) * FA_RS +
                               ks * 16 + kch * 8) * 2;
                    ldsm_x4(bh[j2][ks][0], bh[j2][ks][1], bh[j2][ks][2], bh[j2][ks][3],
                            stb + off);
                }
            float* s0 = sf[4 * jp];     float* s1 = sf[4 * jp + 1];
            float* s2 = sf[4 * jp + 2]; float* s3 = sf[4 * jp + 3];
#pragma unroll
            for (int ks = 0; ks < 4; ks++) {
                mma16816h(s0, qf[ks], &bh[0][ks][0]);
                mma16816h(s1, qf[ks], &bh[0][ks][2]);
                mma16816h(s2, qf[ks], &bh[1][ks][0]);
                mma16816h(s3, qf[ks], &bh[1][ks][2]);
            }
        }

        // ---- online softmax (logits already exp2-domain) ----
        float mt0 = -CUDART_INF_F, mt1 = -CUDART_INF_F;
#pragma unroll
        for (int j = 0; j < 16; j++) {
            mt0 = fmaxf(mt0, fmaxf(sf[j][0], sf[j][1]));
            mt1 = fmaxf(mt1, fmaxf(sf[j][2], sf[j][3]));
        }
        mt0 = fmaxf(mt0, __shfl_xor_sync(0xffffffffu, mt0, 1));
        mt0 = fmaxf(mt0, __shfl_xor_sync(0xffffffffu, mt0, 2));
        mt1 = fmaxf(mt1, __shfl_xor_sync(0xffffffffu, mt1, 1));
        mt1 = fmaxf(mt1, __shfl_xor_sync(0xffffffffu, mt1, 2));
        float mn0 = fmaxf(m0, mt0), mn1 = fmaxf(m1, mt1);
        float f0 = fast_exp2(m0 - mn0), f1 = fast_exp2(m1 - mn1);
        m0 = mn0; m1 = mn1;
        float rs0 = 0.f, rs1 = 0.f;
#pragma unroll
        for (int j = 0; j < 16; j++) {
            sf[j][0] = fast_exp2(sf[j][0] - mn0);
            sf[j][1] = fast_exp2(sf[j][1] - mn0);
            sf[j][2] = fast_exp2(sf[j][2] - mn1);
            sf[j][3] = fast_exp2(sf[j][3] - mn1);
            rs0 += sf[j][0] + sf[j][1];
            rs1 += sf[j][2] + sf[j][3];
        }
        rs0 += __shfl_xor_sync(0xffffffffu, rs0, 1);
        rs0 += __shfl_xor_sync(0xffffffffu, rs0, 2);
        rs1 += __shfl_xor_sync(0xffffffffu, rs1, 1);
        rs1 += __shfl_xor_sync(0xffffffffu, rs1, 2);
        l0 = l0 * f0 + rs0;
        l1 = l1 * f1 + rs1;
#pragma unroll
        for (int j = 0; j < 8; j++) {
            of[j][0] *= f0; of[j][1] *= f0; of[j][2] *= f1; of[j][3] *= f1;
        }

        // ---- O += P V (single fp16 pass) ----
#pragma unroll
        for (int kp = 0; kp < 8; kp++) {
            u32 ah[4];
            ah[0] = cvt_f16x2(sf[2 * kp][0],     sf[2 * kp][1]);
            ah[1] = cvt_f16x2(sf[2 * kp][2],     sf[2 * kp][3]);
            ah[2] = cvt_f16x2(sf[2 * kp + 1][0], sf[2 * kp + 1][1]);
            ah[3] = cvt_f16x2(sf[2 * kp + 1][2], sf[2 * kp + 1][3]);
            u32 bv[4][4];
#pragma unroll
            for (int dt = 0; dt < 4; dt++) {
                u32 off = ((kp * 16 + vrow) * FA_RS + dt * 16 + vch * 8) * 2;
                ldsm_x4t(bv[dt][0], bv[dt][1], bv[dt][2], bv[dt][3],
                         stb + FA_KVARR * 2 + off);
            }
#pragma unroll
            for (int dt = 0; dt < 4; dt++) {
                mma16816h(of[2 * dt],     ah, &bv[dt][0]);
                mma16816h(of[2 * dt + 1], ah, &bv[dt][2]);
            }
        }
        __syncthreads();
    }

    // ---- epilogue: normalize, store single fp16 ----
    float inv0 = 1.f / l0, inv1 = 1.f / l1;
    const int g = lane >> 2, t2 = (lane & 3) * 2;
    size_t r0 = rowbase + qt * 64 + w * 16 + g;
#pragma unroll
    for (int j = 0; j < 8; j++) {
        int c = colbase + j * 8 + t2;
        u32 v0 = cvt_f16x2(of[j][0] * inv0, of[j][1] * inv0);
        u32 v1 = cvt_f16x2(of[j][2] * inv1, of[j][3] * inv1);
        *(u32*)(o16 + r0 * C_DIM + c) = v0;
        *(u32*)(o16 + (r0 + 8) * C_DIM + c) = v1;
    }
#undef FA_LOAD
}

// ---------------------------------------------------------------------------
extern "C" void kernel_launch(void* const* d_in, const int* in_sizes, int n_in,
                              void* d_out, int out_size)
{
    const float* x     = (const float*)d_in[0];
    const float* Wqkv  = (const float*)d_in[1];
    const float* bqkv  = (const float*)d_in[2];
    const float* Wproj = (const float*)d_in[3];
    const float* bproj = (const float*)d_in[4];
    float* out = (float*)d_out;

    __half *q16, *k16, *v16, *xh16, *xl16, *o16, *wq16, *wp16;
    cudaGetSymbolAddress((void**)&q16, g_q16);
    cudaGetSymbolAddress((void**)&k16, g_k16);   cudaGetSymbolAddress((void**)&v16, g_v16);
    cudaGetSymbolAddress((void**)&xh16, g_xh16); cudaGetSymbolAddress((void**)&xl16, g_xl16);
    cudaGetSymbolAddress((void**)&o16, g_o16);
    cudaGetSymbolAddress((void**)&wq16, g_wq16); cudaGetSymbolAddress((void**)&wp16, g_wp16);

    const int SM_QKV  = 2 * 3 * ARR_B;   // 61440 B
    const int SM_PROJ = 2 * 2 * ARR_B;   // 40960 B
    cudaFuncSetAttribute((const void*)gemm_f16_kernel<2, 1>,
                         cudaFuncAttributeMaxDynamicSharedMemorySize, SM_QKV);
    cudaFuncSetAttribute((const void*)gemm_f16_kernel<1, 0>,
                         cudaFuncAttributeMaxDynamicSharedMemorySize, SM_PROJ);
    cudaFuncSetAttribute(flash_attn_mma,
                         cudaFuncAttributeMaxDynamicSharedMemorySize, FA_SMEM);

    // prep: x -> fp16 hi/lo; both weights transposed in ONE launch
    split16_kernel<<<(M_ROWS * C_DIM / 4 + 255) / 256, 256>>>(
        x, xh16, xl16, M_ROWS * C_DIM / 4);
    transpose_both_kernel<<<dim3(C3 / 32, C_DIM / 32, 2), dim3(32, 8)>>>(
        Wqkv, Wproj, wq16, wp16);

    // 1) qkv projection: q 2-pass (pre-scaled by QSC), k/v single-pass
    gemm_f16_kernel<2, 1><<<dim3(C3 / 128, M_ROWS / 128), 128, SM_QKV>>>(
        xh16, xl16, wq16, bqkv, nullptr, M_ROWS, C3, C_DIM,
        q16, k16, v16);

    // 2) attention -> single fp16 (64-row q tiles, 2 CTAs/SM)
    flash_attn_mma<<<dim3(T_SZ / 64, B_SZ * NH), 128, FA_SMEM>>>(
        q16, k16, v16, o16);

    // 3) out = attn @ Wproj + bproj (fp16 single-pass)
    gemm_f16_kernel<1, 0><<<dim3(C_DIM / 128, M_ROWS / 128), 128, SM_PROJ>>>(
        o16, nullptr, wp16, bproj, out, M_ROWS, C_DIM, C_DIM,
        nullptr, nullptr, nullptr);
}